// round 2
// baseline (speedup 1.0000x reference)
#include <cuda_runtime.h>
#include <cstdint>
#include <math.h>

#define NN 8
#define BB 64
#define TT 256
#define INP 64
#define HH 512
#define GG 2048   /* 4*H */
#define MM 512
#define OO 7

// ---------------- scratch (static device globals; no allocation) ----------------
__device__ float g_z[(size_t)BB * TT * HH];                 // [B][T][H]      32 MB
__device__ float g_xg0[(size_t)TT * NN * BB * GG];          // [T][N][B][4H]   1 GiB
__device__ float g_h0[2][NN * BB * HH];
__device__ float g_h1[2][NN * BB * HH];
__device__ float g_c0[NN * BB * HH];
__device__ float g_c1[NN * BB * HH];
__device__ float g_y[(size_t)NN * BB * TT * HH];            // [N][B][T][H]  256 MB
__device__ float g_hid[(size_t)NN * BB * TT * MM];          // [N][BT][M]    256 MB
__device__ unsigned g_barc;
__device__ unsigned g_barg;

__device__ __forceinline__ float sigf(float x) { return 1.0f / (1.0f + expf(-x)); }

// ---------------- init: zero states + barrier counters ----------------
__global__ void k_init() {
    int i = blockIdx.x * blockDim.x + threadIdx.x;
    int stride = gridDim.x * blockDim.x;
    for (int j = i; j < NN * BB * HH; j += stride) {
        g_h0[0][j] = 0.0f;
        g_h1[0][j] = 0.0f;
        g_c0[j] = 0.0f;
        g_c1[j] = 0.0f;
    }
    if (i == 0) { g_barc = 0u; g_barg = 0u; }
}

// ---------------- input layer: z = leaky(x @ Win^T + bin)*10 ----------------
// tile 64 rows x 128 cols, K=64
__global__ void __launch_bounds__(256) k_input(const float* __restrict__ x,
                                               const float* __restrict__ Win,
                                               const float* __restrict__ bin_) {
    __shared__ __align__(16) float As[16][68];
    __shared__ __align__(16) float Bs[16][132];
    int tid = threadIdx.x;
    int tc = tid & 15, tr = tid >> 4;
    int row0 = blockIdx.x * 64;      // flat (b*T+t)
    int c0 = blockIdx.y * 128;       // h
    float acc[4][8];
#pragma unroll
    for (int i = 0; i < 4; i++)
#pragma unroll
        for (int j = 0; j < 8; j++) acc[i][j] = 0.0f;

    for (int k0 = 0; k0 < INP; k0 += 16) {
        {
            int r = tid >> 2, kq = (tid & 3) * 4;
            float4 v = *(const float4*)(x + (size_t)(row0 + r) * INP + k0 + kq);
            As[kq + 0][r] = v.x; As[kq + 1][r] = v.y; As[kq + 2][r] = v.z; As[kq + 3][r] = v.w;
        }
        {
            int c = tid >> 1, kh = (tid & 1) * 8;
            const float* p = Win + (size_t)(c0 + c) * INP + k0 + kh;
            float4 v0 = *(const float4*)p;
            float4 v1 = *(const float4*)(p + 4);
            Bs[kh + 0][c] = v0.x; Bs[kh + 1][c] = v0.y; Bs[kh + 2][c] = v0.z; Bs[kh + 3][c] = v0.w;
            Bs[kh + 4][c] = v1.x; Bs[kh + 5][c] = v1.y; Bs[kh + 6][c] = v1.z; Bs[kh + 7][c] = v1.w;
        }
        __syncthreads();
#pragma unroll
        for (int kk = 0; kk < 16; kk++) {
            float4 a = *(const float4*)&As[kk][tr * 4];
            float4 b0 = *(const float4*)&Bs[kk][tc * 8];
            float4 b1 = *(const float4*)&Bs[kk][tc * 8 + 4];
            float av[4] = {a.x, a.y, a.z, a.w};
            float bv[8] = {b0.x, b0.y, b0.z, b0.w, b1.x, b1.y, b1.z, b1.w};
#pragma unroll
            for (int i = 0; i < 4; i++)
#pragma unroll
                for (int j = 0; j < 8; j++) acc[i][j] = fmaf(av[i], bv[j], acc[i][j]);
        }
        __syncthreads();
    }
#pragma unroll
    for (int i = 0; i < 4; i++) {
        int row = row0 + tr * 4 + i;
#pragma unroll
        for (int j = 0; j < 8; j++) {
            int h = c0 + tc * 8 + j;
            float v = acc[i][j] + bin_[h];
            v = (v > 0.0f ? v : 0.2f * v) * 10.0f;
            g_z[(size_t)row * HH + h] = v;
        }
    }
}

// ---------------- xg0 precompute: xg0[t][n][b][gc] = z[b,t,:] @ W_ih0[n,gc,:] + b_ih0 + b_hh0 ----------------
// tile: 64 t-rows (fixed b) x 128 gate-cols, K=512
__global__ void __launch_bounds__(256) k_xg0(const float* __restrict__ W_ih0,
                                             const float* __restrict__ b_ih0,
                                             const float* __restrict__ b_hh0) {
    __shared__ __align__(16) float As[16][68];
    __shared__ __align__(16) float Bs[16][132];
    int tid = threadIdx.x;
    int tc = tid & 15, tr = tid >> 4;
    int rt = blockIdx.x;
    int b = rt >> 2;
    int t0 = (rt & 3) * 64;
    int gc0 = blockIdx.y * 128;
    int n = blockIdx.z;
    const float* Abase = g_z + ((size_t)b * TT + t0) * HH;
    const float* Bbase = W_ih0 + (size_t)n * GG * HH + (size_t)gc0 * HH;
    float acc[4][8];
#pragma unroll
    for (int i = 0; i < 4; i++)
#pragma unroll
        for (int j = 0; j < 8; j++) acc[i][j] = 0.0f;

    for (int k0 = 0; k0 < HH; k0 += 16) {
        {
            int r = tid >> 2, kq = (tid & 3) * 4;
            float4 v = *(const float4*)(Abase + (size_t)r * HH + k0 + kq);
            As[kq + 0][r] = v.x; As[kq + 1][r] = v.y; As[kq + 2][r] = v.z; As[kq + 3][r] = v.w;
        }
        {
            int c = tid >> 1, kh = (tid & 1) * 8;
            const float* p = Bbase + (size_t)c * HH + k0 + kh;
            float4 v0 = *(const float4*)p;
            float4 v1 = *(const float4*)(p + 4);
            Bs[kh + 0][c] = v0.x; Bs[kh + 1][c] = v0.y; Bs[kh + 2][c] = v0.z; Bs[kh + 3][c] = v0.w;
            Bs[kh + 4][c] = v1.x; Bs[kh + 5][c] = v1.y; Bs[kh + 6][c] = v1.z; Bs[kh + 7][c] = v1.w;
        }
        __syncthreads();
#pragma unroll
        for (int kk = 0; kk < 16; kk++) {
            float4 a = *(const float4*)&As[kk][tr * 4];
            float4 b0 = *(const float4*)&Bs[kk][tc * 8];
            float4 b1 = *(const float4*)&Bs[kk][tc * 8 + 4];
            float av[4] = {a.x, a.y, a.z, a.w};
            float bv[8] = {b0.x, b0.y, b0.z, b0.w, b1.x, b1.y, b1.z, b1.w};
#pragma unroll
            for (int i = 0; i < 4; i++)
#pragma unroll
                for (int j = 0; j < 8; j++) acc[i][j] = fmaf(av[i], bv[j], acc[i][j]);
        }
        __syncthreads();
    }
#pragma unroll
    for (int i = 0; i < 4; i++) {
        int t = t0 + tr * 4 + i;
        size_t ob = ((size_t)t * NN + n) * (BB * GG) + (size_t)b * GG;
#pragma unroll
        for (int j = 0; j < 8; j++) {
            int gc = gc0 + tc * 8 + j;
            g_xg0[ob + gc] = acc[i][j] + b_ih0[(size_t)n * GG + gc] + b_hh0[(size_t)n * GG + gc];
        }
    }
}

// ---------------- grid barrier (all blocks co-resident by construction) ----------------
__device__ __forceinline__ void grid_bar(unsigned nb) {
    __syncthreads();
    if (threadIdx.x == 0) {
        __threadfence();
        unsigned gen = atomicAdd(&g_barg, 0u);
        unsigned t = atomicAdd(&g_barc, 1u);
        if (t == nb - 1u) {
            atomicExch(&g_barc, 0u);
            __threadfence();
            atomicAdd(&g_barg, 1u);
        } else {
            while (atomicAdd(&g_barg, 0u) == gen) { __nanosleep(64); }
        }
        __threadfence();
    }
    __syncthreads();
}

// recurrent GEMM fragment: rows = 64 batch, cols = 64 = 16 hidden x 4 gates, K = 512
// col c -> weight row = (c&3)*512 + hh0 + (c>>2); thread tc owns hidden hh0+tc, all 4 gates.
__device__ __forceinline__ void rec_gemm(const float* __restrict__ Abase,
                                         const float* __restrict__ Wbase,
                                         int hh0, float (&acc)[4][4],
                                         float (*As)[68], float (*Bs)[68],
                                         int tid, int tr, int tc) {
    for (int k0 = 0; k0 < HH; k0 += 16) {
        int r = tid >> 2, kq = (tid & 3) * 4;
        float4 av = *(const float4*)(Abase + (size_t)r * HH + k0 + kq);
        As[kq + 0][r] = av.x; As[kq + 1][r] = av.y; As[kq + 2][r] = av.z; As[kq + 3][r] = av.w;
        int cc = r;  // same mapping reused for B cols
        int wrow = (cc & 3) * HH + hh0 + (cc >> 2);
        float4 bv = *(const float4*)(Wbase + (size_t)wrow * HH + k0 + kq);
        Bs[kq + 0][cc] = bv.x; Bs[kq + 1][cc] = bv.y; Bs[kq + 2][cc] = bv.z; Bs[kq + 3][cc] = bv.w;
        __syncthreads();
#pragma unroll
        for (int kk = 0; kk < 16; kk++) {
            float4 a = *(const float4*)&As[kk][tr * 4];
            float4 b = *(const float4*)&Bs[kk][tc * 4];
            float av2[4] = {a.x, a.y, a.z, a.w};
            float bv2[4] = {b.x, b.y, b.z, b.w};
#pragma unroll
            for (int i = 0; i < 4; i++)
#pragma unroll
                for (int j = 0; j < 4; j++) acc[i][j] = fmaf(av2[i], bv2[j], acc[i][j]);
        }
        __syncthreads();
    }
}

// ---------------- persistent sequential LSTM (both layers), 256 blocks ----------------
__global__ void __launch_bounds__(256) k_rec(const float* __restrict__ W_hh0,
                                             const float* __restrict__ W_ih1,
                                             const float* __restrict__ W_hh1,
                                             const float* __restrict__ b_ih1,
                                             const float* __restrict__ b_hh1) {
    __shared__ __align__(16) float As[16][68];
    __shared__ __align__(16) float Bs[16][68];
    int tid = threadIdx.x;
    int tc = tid & 15, tr = tid >> 4;
    int n = blockIdx.x >> 5;      // 8 generators
    int ct = blockIdx.x & 31;     // 32 column tiles of 16 hidden units
    int hh0 = ct * 16;
    unsigned nb = gridDim.x;
    const float* Whh0n = W_hh0 + (size_t)n * GG * HH;
    const float* Wih1n = W_ih1 + (size_t)n * GG * HH;
    const float* Whh1n = W_hh1 + (size_t)n * GG * HH;
    size_t st = (size_t)n * BB * HH;
    int h = hh0 + tc;

    float bias1[4];
#pragma unroll
    for (int g = 0; g < 4; g++)
        bias1[g] = b_ih1[(size_t)n * GG + g * HH + h] + b_hh1[(size_t)n * GG + g * HH + h];

    for (int t = 0; t < TT; t++) {
        int p = t & 1;
        // ---- layer 0 ----
        float acc[4][4];
#pragma unroll
        for (int i = 0; i < 4; i++)
#pragma unroll
            for (int j = 0; j < 4; j++) acc[i][j] = 0.0f;
        rec_gemm(g_h0[p] + st, Whh0n, hh0, acc, As, Bs, tid, tr, tc);
        {
            const float* xg = g_xg0 + ((size_t)t * NN + n) * ((size_t)BB * GG);
#pragma unroll
            for (int i = 0; i < 4; i++) {
                int b = tr * 4 + i;
                const float* xgb = xg + (size_t)b * GG;
                float pi = acc[i][0] + xgb[h];
                float pf = acc[i][1] + xgb[HH + h];
                float pg = acc[i][2] + xgb[2 * HH + h];
                float po = acc[i][3] + xgb[3 * HH + h];
                size_t idx = st + (size_t)b * HH + h;
                float co = g_c0[idx];
                float cn = sigf(pf) * co + sigf(pi) * tanhf(pg);
                float hn = sigf(po) * tanhf(cn);
                g_c0[idx] = cn;
                g_h0[p ^ 1][idx] = hn;
            }
        }
        grid_bar(nb);
        // ---- layer 1 ----
#pragma unroll
        for (int i = 0; i < 4; i++)
#pragma unroll
            for (int j = 0; j < 4; j++) acc[i][j] = 0.0f;
        rec_gemm(g_h0[p ^ 1] + st, Wih1n, hh0, acc, As, Bs, tid, tr, tc);
        rec_gemm(g_h1[p] + st, Whh1n, hh0, acc, As, Bs, tid, tr, tc);
        {
#pragma unroll
            for (int i = 0; i < 4; i++) {
                int b = tr * 4 + i;
                float pi = acc[i][0] + bias1[0];
                float pf = acc[i][1] + bias1[1];
                float pg = acc[i][2] + bias1[2];
                float po = acc[i][3] + bias1[3];
                size_t idx = st + (size_t)b * HH + h;
                float co = g_c1[idx];
                float cn = sigf(pf) * co + sigf(pi) * tanhf(pg);
                float hn = sigf(po) * tanhf(cn);
                g_c1[idx] = cn;
                g_h1[p ^ 1][idx] = hn;
                g_y[(((size_t)n * BB + b) * TT + t) * HH + h] = hn;
            }
        }
        grid_bar(nb);
    }
}

// ---------------- heads stage 1: hid = leaky(y @ Wh1^T + bh1) ----------------
__global__ void __launch_bounds__(256) k_heads1(const float* __restrict__ Wh1,
                                                const float* __restrict__ bh1) {
    __shared__ __align__(16) float As[16][68];
    __shared__ __align__(16) float Bs[16][132];
    int tid = threadIdx.x;
    int tc = tid & 15, tr = tid >> 4;
    int row0 = blockIdx.x * 64;       // bt rows
    int m0 = blockIdx.y * 128;
    int n = blockIdx.z;
    const float* Abase = g_y + ((size_t)n * BB * TT + row0) * HH;
    const float* Bbase = Wh1 + (size_t)n * MM * HH + (size_t)m0 * HH;
    float acc[4][8];
#pragma unroll
    for (int i = 0; i < 4; i++)
#pragma unroll
        for (int j = 0; j < 8; j++) acc[i][j] = 0.0f;

    for (int k0 = 0; k0 < HH; k0 += 16) {
        {
            int r = tid >> 2, kq = (tid & 3) * 4;
            float4 v = *(const float4*)(Abase + (size_t)r * HH + k0 + kq);
            As[kq + 0][r] = v.x; As[kq + 1][r] = v.y; As[kq + 2][r] = v.z; As[kq + 3][r] = v.w;
        }
        {
            int c = tid >> 1, kh = (tid & 1) * 8;
            const float* p = Bbase + (size_t)c * HH + k0 + kh;
            float4 v0 = *(const float4*)p;
            float4 v1 = *(const float4*)(p + 4);
            Bs[kh + 0][c] = v0.x; Bs[kh + 1][c] = v0.y; Bs[kh + 2][c] = v0.z; Bs[kh + 3][c] = v0.w;
            Bs[kh + 4][c] = v1.x; Bs[kh + 5][c] = v1.y; Bs[kh + 6][c] = v1.z; Bs[kh + 7][c] = v1.w;
        }
        __syncthreads();
#pragma unroll
        for (int kk = 0; kk < 16; kk++) {
            float4 a = *(const float4*)&As[kk][tr * 4];
            float4 b0 = *(const float4*)&Bs[kk][tc * 8];
            float4 b1 = *(const float4*)&Bs[kk][tc * 8 + 4];
            float av[4] = {a.x, a.y, a.z, a.w};
            float bv[8] = {b0.x, b0.y, b0.z, b0.w, b1.x, b1.y, b1.z, b1.w};
#pragma unroll
            for (int i = 0; i < 4; i++)
#pragma unroll
                for (int j = 0; j < 8; j++) acc[i][j] = fmaf(av[i], bv[j], acc[i][j]);
        }
        __syncthreads();
    }
#pragma unroll
    for (int i = 0; i < 4; i++) {
        int row = row0 + tr * 4 + i;
#pragma unroll
        for (int j = 0; j < 8; j++) {
            int m = m0 + tc * 8 + j;
            float v = acc[i][j] + bh1[(size_t)n * MM + m];
            v = (v > 0.0f ? v : 0.2f * v);
            g_hid[((size_t)n * BB * TT + row) * MM + m] = v;
        }
    }
}

// ---------------- heads stage 2: out = hid @ Wh2^T + bh2 (warp per row) ----------------
__global__ void __launch_bounds__(256) k_heads2(const float* __restrict__ Wh2,
                                                const float* __restrict__ bh2,
                                                float* __restrict__ out) {
    int gw = (blockIdx.x * blockDim.x + threadIdx.x) >> 5;
    int lane = threadIdx.x & 31;
    if (gw >= NN * BB * TT) return;
    int n = gw >> 14;  // / 16384
    const float* hrow = g_hid + (size_t)gw * MM;
    float hv[16];
#pragma unroll
    for (int q = 0; q < 4; q++) {
        float4 v = *(const float4*)(hrow + lane * 16 + q * 4);
        hv[q * 4 + 0] = v.x; hv[q * 4 + 1] = v.y; hv[q * 4 + 2] = v.z; hv[q * 4 + 3] = v.w;
    }
    const float* W = Wh2 + (size_t)n * OO * MM;
#pragma unroll
    for (int o = 0; o < OO; o++) {
        const float4* w4 = (const float4*)(W + (size_t)o * MM + lane * 16);
        float s = 0.0f;
#pragma unroll
        for (int q = 0; q < 4; q++) {
            float4 w = w4[q];
            s += hv[q * 4 + 0] * w.x + hv[q * 4 + 1] * w.y + hv[q * 4 + 2] * w.z + hv[q * 4 + 3] * w.w;
        }
#pragma unroll
        for (int off = 16; off > 0; off >>= 1) s += __shfl_xor_sync(0xFFFFFFFFu, s, off);
        if (lane == 0) out[(size_t)gw * OO + o] = s + bh2[(size_t)n * OO + o];
    }
}

// ---------------- launch ----------------
extern "C" void kernel_launch(void* const* d_in, const int* in_sizes, int n_in,
                              void* d_out, int out_size) {
    const float* x     = (const float*)d_in[0];
    const float* Win   = (const float*)d_in[1];
    const float* bin_  = (const float*)d_in[2];
    const float* W_ih0 = (const float*)d_in[3];
    const float* W_hh0 = (const float*)d_in[4];
    const float* b_ih0 = (const float*)d_in[5];
    const float* b_hh0 = (const float*)d_in[6];
    const float* W_ih1 = (const float*)d_in[7];
    const float* W_hh1 = (const float*)d_in[8];
    const float* b_ih1 = (const float*)d_in[9];
    const float* b_hh1 = (const float*)d_in[10];
    const float* Wh1   = (const float*)d_in[11];
    const float* bh1   = (const float*)d_in[12];
    const float* Wh2   = (const float*)d_in[13];
    const float* bh2   = (const float*)d_in[14];
    float* out = (float*)d_out;

    k_init<<<256, 256>>>();
    k_input<<<dim3(BB * TT / 64, HH / 128), 256>>>(x, Win, bin_);
    k_xg0<<<dim3(BB * 4, GG / 128, NN), 256>>>(W_ih0, b_ih0, b_hh0);
    k_rec<<<256, 256>>>(W_hh0, W_ih1, W_hh1, b_ih1, b_hh1);
    k_heads1<<<dim3(BB * TT / 64, MM / 128, NN), 256>>>(Wh1, bh1);
    k_heads2<<<(NN * BB * TT) / 8, 256>>>(Wh2, bh2, out);
}

// round 3
// speedup vs baseline: 1.0046x; 1.0046x over previous
#include <cuda_runtime.h>
#include <cstdint>
#include <math.h>

#define NN 8
#define BB 64
#define TT 256
#define INP 64
#define HH 512
#define GG 2048   /* 4*H */
#define MM 512
#define OO 7

// ---------------- scratch (static device globals; no allocation) ----------------
__device__ float g_z[(size_t)BB * TT * HH];                 // [B][T][H]      32 MB
__device__ float g_xg0[(size_t)TT * NN * BB * GG];          // [T][N][B][4H]   1 GiB
__device__ float g_h0[2][NN * BB * HH];
__device__ float g_h1[2][NN * BB * HH];
__device__ float g_c0[NN * BB * HH];
__device__ float g_c1[NN * BB * HH];
__device__ float g_y[(size_t)NN * BB * TT * HH];            // [N][B][T][H]  256 MB
__device__ float g_hid[(size_t)NN * BB * TT * MM];          // [N][BT][M]    256 MB
__device__ unsigned g_barc;
__device__ unsigned g_barg;

__device__ __forceinline__ float sigf(float x) { return 1.0f / (1.0f + expf(-x)); }

// ---------------- init: zero states + barrier counters ----------------
__global__ void k_init() {
    int i = blockIdx.x * blockDim.x + threadIdx.x;
    int stride = gridDim.x * blockDim.x;
    for (int j = i; j < NN * BB * HH; j += stride) {
        g_h0[0][j] = 0.0f;
        g_h1[0][j] = 0.0f;
        g_c0[j] = 0.0f;
        g_c1[j] = 0.0f;
    }
    if (i == 0) { g_barc = 0u; g_barg = 0u; }
}

// ---------------- input layer: z = leaky(x @ Win^T + bin)*10 ----------------
// tile 64 rows x 128 cols, K=64
__global__ void __launch_bounds__(256) k_input(const float* __restrict__ x,
                                               const float* __restrict__ Win,
                                               const float* __restrict__ bin_) {
    __shared__ __align__(16) float As[16][68];
    __shared__ __align__(16) float Bs[16][132];
    int tid = threadIdx.x;
    int tc = tid & 15, tr = tid >> 4;
    int row0 = blockIdx.x * 64;      // flat (b*T+t)
    int c0 = blockIdx.y * 128;       // h
    float acc[4][8];
#pragma unroll
    for (int i = 0; i < 4; i++)
#pragma unroll
        for (int j = 0; j < 8; j++) acc[i][j] = 0.0f;

    for (int k0 = 0; k0 < INP; k0 += 16) {
        {
            int r = tid >> 2, kq = (tid & 3) * 4;
            float4 v = *(const float4*)(x + (size_t)(row0 + r) * INP + k0 + kq);
            As[kq + 0][r] = v.x; As[kq + 1][r] = v.y; As[kq + 2][r] = v.z; As[kq + 3][r] = v.w;
        }
        {
            int c = tid >> 1, kh = (tid & 1) * 8;
            const float* p = Win + (size_t)(c0 + c) * INP + k0 + kh;
            float4 v0 = *(const float4*)p;
            float4 v1 = *(const float4*)(p + 4);
            Bs[kh + 0][c] = v0.x; Bs[kh + 1][c] = v0.y; Bs[kh + 2][c] = v0.z; Bs[kh + 3][c] = v0.w;
            Bs[kh + 4][c] = v1.x; Bs[kh + 5][c] = v1.y; Bs[kh + 6][c] = v1.z; Bs[kh + 7][c] = v1.w;
        }
        __syncthreads();
#pragma unroll
        for (int kk = 0; kk < 16; kk++) {
            float4 a = *(const float4*)&As[kk][tr * 4];
            float4 b0 = *(const float4*)&Bs[kk][tc * 8];
            float4 b1 = *(const float4*)&Bs[kk][tc * 8 + 4];
            float av[4] = {a.x, a.y, a.z, a.w};
            float bv[8] = {b0.x, b0.y, b0.z, b0.w, b1.x, b1.y, b1.z, b1.w};
#pragma unroll
            for (int i = 0; i < 4; i++)
#pragma unroll
                for (int j = 0; j < 8; j++) acc[i][j] = fmaf(av[i], bv[j], acc[i][j]);
        }
        __syncthreads();
    }
#pragma unroll
    for (int i = 0; i < 4; i++) {
        int row = row0 + tr * 4 + i;
#pragma unroll
        for (int j = 0; j < 8; j++) {
            int h = c0 + tc * 8 + j;
            float v = acc[i][j] + bin_[h];
            v = (v > 0.0f ? v : 0.2f * v) * 10.0f;
            g_z[(size_t)row * HH + h] = v;
        }
    }
}

// ---------------- xg0 precompute: xg0[t][n][b][gc] = z[b,t,:] @ W_ih0[n,gc,:] + b_ih0 + b_hh0 ----------------
// tile: 64 t-rows (fixed b) x 128 gate-cols, K=512
__global__ void __launch_bounds__(256) k_xg0(const float* __restrict__ W_ih0,
                                             const float* __restrict__ b_ih0,
                                             const float* __restrict__ b_hh0) {
    __shared__ __align__(16) float As[16][68];
    __shared__ __align__(16) float Bs[16][132];
    int tid = threadIdx.x;
    int tc = tid & 15, tr = tid >> 4;
    int rt = blockIdx.x;
    int b = rt >> 2;
    int t0 = (rt & 3) * 64;
    int gc0 = blockIdx.y * 128;
    int n = blockIdx.z;
    const float* Abase = g_z + ((size_t)b * TT + t0) * HH;
    const float* Bbase = W_ih0 + (size_t)n * GG * HH + (size_t)gc0 * HH;
    float acc[4][8];
#pragma unroll
    for (int i = 0; i < 4; i++)
#pragma unroll
        for (int j = 0; j < 8; j++) acc[i][j] = 0.0f;

    for (int k0 = 0; k0 < HH; k0 += 16) {
        {
            int r = tid >> 2, kq = (tid & 3) * 4;
            float4 v = *(const float4*)(Abase + (size_t)r * HH + k0 + kq);
            As[kq + 0][r] = v.x; As[kq + 1][r] = v.y; As[kq + 2][r] = v.z; As[kq + 3][r] = v.w;
        }
        {
            int c = tid >> 1, kh = (tid & 1) * 8;
            const float* p = Bbase + (size_t)c * HH + k0 + kh;
            float4 v0 = *(const float4*)p;
            float4 v1 = *(const float4*)(p + 4);
            Bs[kh + 0][c] = v0.x; Bs[kh + 1][c] = v0.y; Bs[kh + 2][c] = v0.z; Bs[kh + 3][c] = v0.w;
            Bs[kh + 4][c] = v1.x; Bs[kh + 5][c] = v1.y; Bs[kh + 6][c] = v1.z; Bs[kh + 7][c] = v1.w;
        }
        __syncthreads();
#pragma unroll
        for (int kk = 0; kk < 16; kk++) {
            float4 a = *(const float4*)&As[kk][tr * 4];
            float4 b0 = *(const float4*)&Bs[kk][tc * 8];
            float4 b1 = *(const float4*)&Bs[kk][tc * 8 + 4];
            float av[4] = {a.x, a.y, a.z, a.w};
            float bv[8] = {b0.x, b0.y, b0.z, b0.w, b1.x, b1.y, b1.z, b1.w};
#pragma unroll
            for (int i = 0; i < 4; i++)
#pragma unroll
                for (int j = 0; j < 8; j++) acc[i][j] = fmaf(av[i], bv[j], acc[i][j]);
        }
        __syncthreads();
    }
#pragma unroll
    for (int i = 0; i < 4; i++) {
        int t = t0 + tr * 4 + i;
        size_t ob = ((size_t)t * NN + n) * (BB * GG) + (size_t)b * GG;
#pragma unroll
        for (int j = 0; j < 8; j++) {
            int gc = gc0 + tc * 8 + j;
            g_xg0[ob + gc] = acc[i][j] + b_ih0[(size_t)n * GG + gc] + b_hh0[(size_t)n * GG + gc];
        }
    }
}

// ---------------- grid barrier (all blocks co-resident by construction) ----------------
__device__ __forceinline__ void grid_bar(unsigned nb) {
    __syncthreads();
    if (threadIdx.x == 0) {
        __threadfence();
        unsigned gen = atomicAdd(&g_barg, 0u);
        unsigned t = atomicAdd(&g_barc, 1u);
        if (t == nb - 1u) {
            atomicExch(&g_barc, 0u);
            __threadfence();
            atomicAdd(&g_barg, 1u);
        } else {
            while (atomicAdd(&g_barg, 0u) == gen) { __nanosleep(64); }
        }
        __threadfence();
    }
    __syncthreads();
}

// recurrent GEMM fragment: rows = 64 batch, cols = 64 = 16 hidden x 4 gates, K = 512
// col c -> weight row = (c&3)*512 + hh0 + (c>>2); thread tc owns hidden hh0+tc, all 4 gates.
__device__ __forceinline__ void rec_gemm(const float* __restrict__ Abase,
                                         const float* __restrict__ Wbase,
                                         int hh0, float (&acc)[4][4],
                                         float (*As)[68], float (*Bs)[68],
                                         int tid, int tr, int tc) {
    for (int k0 = 0; k0 < HH; k0 += 16) {
        int r = tid >> 2, kq = (tid & 3) * 4;
        float4 av = *(const float4*)(Abase + (size_t)r * HH + k0 + kq);
        As[kq + 0][r] = av.x; As[kq + 1][r] = av.y; As[kq + 2][r] = av.z; As[kq + 3][r] = av.w;
        int cc = r;  // same mapping reused for B cols
        int wrow = (cc & 3) * HH + hh0 + (cc >> 2);
        float4 bv = *(const float4*)(Wbase + (size_t)wrow * HH + k0 + kq);
        Bs[kq + 0][cc] = bv.x; Bs[kq + 1][cc] = bv.y; Bs[kq + 2][cc] = bv.z; Bs[kq + 3][cc] = bv.w;
        __syncthreads();
#pragma unroll
        for (int kk = 0; kk < 16; kk++) {
            float4 a = *(const float4*)&As[kk][tr * 4];
            float4 b = *(const float4*)&Bs[kk][tc * 4];
            float av2[4] = {a.x, a.y, a.z, a.w};
            float bv2[4] = {b.x, b.y, b.z, b.w};
#pragma unroll
            for (int i = 0; i < 4; i++)
#pragma unroll
                for (int j = 0; j < 4; j++) acc[i][j] = fmaf(av2[i], bv2[j], acc[i][j]);
        }
        __syncthreads();
    }
}

// ---------------- persistent sequential LSTM (both layers), 256 blocks ----------------
__global__ void __launch_bounds__(256) k_rec(const float* __restrict__ W_hh0,
                                             const float* __restrict__ W_ih1,
                                             const float* __restrict__ W_hh1,
                                             const float* __restrict__ b_ih1,
                                             const float* __restrict__ b_hh1) {
    __shared__ __align__(16) float As[16][68];
    __shared__ __align__(16) float Bs[16][68];
    int tid = threadIdx.x;
    int tc = tid & 15, tr = tid >> 4;
    int n = blockIdx.x >> 5;      // 8 generators
    int ct = blockIdx.x & 31;     // 32 column tiles of 16 hidden units
    int hh0 = ct * 16;
    unsigned nb = gridDim.x;
    const float* Whh0n = W_hh0 + (size_t)n * GG * HH;
    const float* Wih1n = W_ih1 + (size_t)n * GG * HH;
    const float* Whh1n = W_hh1 + (size_t)n * GG * HH;
    size_t st = (size_t)n * BB * HH;
    int h = hh0 + tc;

    float bias1[4];
#pragma unroll
    for (int g = 0; g < 4; g++)
        bias1[g] = b_ih1[(size_t)n * GG + g * HH + h] + b_hh1[(size_t)n * GG + g * HH + h];

    for (int t = 0; t < TT; t++) {
        int p = t & 1;
        // ---- layer 0 ----
        float acc[4][4];
#pragma unroll
        for (int i = 0; i < 4; i++)
#pragma unroll
            for (int j = 0; j < 4; j++) acc[i][j] = 0.0f;
        rec_gemm(g_h0[p] + st, Whh0n, hh0, acc, As, Bs, tid, tr, tc);
        {
            const float* xg = g_xg0 + ((size_t)t * NN + n) * ((size_t)BB * GG);
#pragma unroll
            for (int i = 0; i < 4; i++) {
                int b = tr * 4 + i;
                const float* xgb = xg + (size_t)b * GG;
                float pi = acc[i][0] + xgb[h];
                float pf = acc[i][1] + xgb[HH + h];
                float pg = acc[i][2] + xgb[2 * HH + h];
                float po = acc[i][3] + xgb[3 * HH + h];
                size_t idx = st + (size_t)b * HH + h;
                float co = g_c0[idx];
                float cn = sigf(pf) * co + sigf(pi) * tanhf(pg);
                float hn = sigf(po) * tanhf(cn);
                g_c0[idx] = cn;
                g_h0[p ^ 1][idx] = hn;
            }
        }
        grid_bar(nb);
        // ---- layer 1 ----
#pragma unroll
        for (int i = 0; i < 4; i++)
#pragma unroll
            for (int j = 0; j < 4; j++) acc[i][j] = 0.0f;
        rec_gemm(g_h0[p ^ 1] + st, Wih1n, hh0, acc, As, Bs, tid, tr, tc);
        rec_gemm(g_h1[p] + st, Whh1n, hh0, acc, As, Bs, tid, tr, tc);
        {
#pragma unroll
            for (int i = 0; i < 4; i++) {
                int b = tr * 4 + i;
                float pi = acc[i][0] + bias1[0];
                float pf = acc[i][1] + bias1[1];
                float pg = acc[i][2] + bias1[2];
                float po = acc[i][3] + bias1[3];
                size_t idx = st + (size_t)b * HH + h;
                float co = g_c1[idx];
                float cn = sigf(pf) * co + sigf(pi) * tanhf(pg);
                float hn = sigf(po) * tanhf(cn);
                g_c1[idx] = cn;
                g_h1[p ^ 1][idx] = hn;
                g_y[(((size_t)n * BB + b) * TT + t) * HH + h] = hn;
            }
        }
        grid_bar(nb);
    }
}

// ---------------- heads stage 1: hid = leaky(y @ Wh1^T + bh1) ----------------
__global__ void __launch_bounds__(256) k_heads1(const float* __restrict__ Wh1,
                                                const float* __restrict__ bh1) {
    __shared__ __align__(16) float As[16][68];
    __shared__ __align__(16) float Bs[16][132];
    int tid = threadIdx.x;
    int tc = tid & 15, tr = tid >> 4;
    int row0 = blockIdx.x * 64;       // bt rows
    int m0 = blockIdx.y * 128;
    int n = blockIdx.z;
    const float* Abase = g_y + ((size_t)n * BB * TT + row0) * HH;
    const float* Bbase = Wh1 + (size_t)n * MM * HH + (size_t)m0 * HH;
    float acc[4][8];
#pragma unroll
    for (int i = 0; i < 4; i++)
#pragma unroll
        for (int j = 0; j < 8; j++) acc[i][j] = 0.0f;

    for (int k0 = 0; k0 < HH; k0 += 16) {
        {
            int r = tid >> 2, kq = (tid & 3) * 4;
            float4 v = *(const float4*)(Abase + (size_t)r * HH + k0 + kq);
            As[kq + 0][r] = v.x; As[kq + 1][r] = v.y; As[kq + 2][r] = v.z; As[kq + 3][r] = v.w;
        }
        {
            int c = tid >> 1, kh = (tid & 1) * 8;
            const float* p = Bbase + (size_t)c * HH + k0 + kh;
            float4 v0 = *(const float4*)p;
            float4 v1 = *(const float4*)(p + 4);
            Bs[kh + 0][c] = v0.x; Bs[kh + 1][c] = v0.y; Bs[kh + 2][c] = v0.z; Bs[kh + 3][c] = v0.w;
            Bs[kh + 4][c] = v1.x; Bs[kh + 5][c] = v1.y; Bs[kh + 6][c] = v1.z; Bs[kh + 7][c] = v1.w;
        }
        __syncthreads();
#pragma unroll
        for (int kk = 0; kk < 16; kk++) {
            float4 a = *(const float4*)&As[kk][tr * 4];
            float4 b0 = *(const float4*)&Bs[kk][tc * 8];
            float4 b1 = *(const float4*)&Bs[kk][tc * 8 + 4];
            float av[4] = {a.x, a.y, a.z, a.w};
            float bv[8] = {b0.x, b0.y, b0.z, b0.w, b1.x, b1.y, b1.z, b1.w};
#pragma unroll
            for (int i = 0; i < 4; i++)
#pragma unroll
                for (int j = 0; j < 8; j++) acc[i][j] = fmaf(av[i], bv[j], acc[i][j]);
        }
        __syncthreads();
    }
#pragma unroll
    for (int i = 0; i < 4; i++) {
        int row = row0 + tr * 4 + i;
#pragma unroll
        for (int j = 0; j < 8; j++) {
            int m = m0 + tc * 8 + j;
            float v = acc[i][j] + bh1[(size_t)n * MM + m];
            v = (v > 0.0f ? v : 0.2f * v);
            g_hid[((size_t)n * BB * TT + row) * MM + m] = v;
        }
    }
}

// ---------------- heads stage 2: out = hid @ Wh2^T + bh2 (warp per row) ----------------
__global__ void __launch_bounds__(256) k_heads2(const float* __restrict__ Wh2,
                                                const float* __restrict__ bh2,
                                                float* __restrict__ out) {
    int gw = (blockIdx.x * blockDim.x + threadIdx.x) >> 5;
    int lane = threadIdx.x & 31;
    if (gw >= NN * BB * TT) return;
    int n = gw >> 14;  // / 16384
    const float* hrow = g_hid + (size_t)gw * MM;
    float hv[16];
#pragma unroll
    for (int q = 0; q < 4; q++) {
        float4 v = *(const float4*)(hrow + lane * 16 + q * 4);
        hv[q * 4 + 0] = v.x; hv[q * 4 + 1] = v.y; hv[q * 4 + 2] = v.z; hv[q * 4 + 3] = v.w;
    }
    const float* W = Wh2 + (size_t)n * OO * MM;
#pragma unroll
    for (int o = 0; o < OO; o++) {
        const float4* w4 = (const float4*)(W + (size_t)o * MM + lane * 16);
        float s = 0.0f;
#pragma unroll
        for (int q = 0; q < 4; q++) {
            float4 w = w4[q];
            s += hv[q * 4 + 0] * w.x + hv[q * 4 + 1] * w.y + hv[q * 4 + 2] * w.z + hv[q * 4 + 3] * w.w;
        }
#pragma unroll
        for (int off = 16; off > 0; off >>= 1) s += __shfl_xor_sync(0xFFFFFFFFu, s, off);
        if (lane == 0) out[(size_t)gw * OO + o] = s + bh2[(size_t)n * OO + o];
    }
}

// ---------------- launch ----------------
extern "C" void kernel_launch(void* const* d_in, const int* in_sizes, int n_in,
                              void* d_out, int out_size) {
    const float* x     = (const float*)d_in[0];
    const float* Win   = (const float*)d_in[1];
    const float* bin_  = (const float*)d_in[2];
    const float* W_ih0 = (const float*)d_in[3];
    const float* W_hh0 = (const float*)d_in[4];
    const float* b_ih0 = (const float*)d_in[5];
    const float* b_hh0 = (const float*)d_in[6];
    const float* W_ih1 = (const float*)d_in[7];
    const float* W_hh1 = (const float*)d_in[8];
    const float* b_ih1 = (const float*)d_in[9];
    const float* b_hh1 = (const float*)d_in[10];
    const float* Wh1   = (const float*)d_in[11];
    const float* bh1   = (const float*)d_in[12];
    const float* Wh2   = (const float*)d_in[13];
    const float* bh2   = (const float*)d_in[14];
    float* out = (float*)d_out;

    k_init<<<256, 256>>>();
    k_input<<<dim3(BB * TT / 64, HH / 128), 256>>>(x, Win, bin_);
    k_xg0<<<dim3(BB * 4, GG / 128, NN), 256>>>(W_ih0, b_ih0, b_hh0);
    k_rec<<<256, 256>>>(W_hh0, W_ih1, W_hh1, b_ih1, b_hh1);
    k_heads1<<<dim3(BB * TT / 64, MM / 128, NN), 256>>>(Wh1, bh1);
    k_heads2<<<(NN * BB * TT) / 8, 256>>>(Wh2, bh2, out);
}

// round 4
// speedup vs baseline: 2.5466x; 2.5349x over previous
#include <cuda_runtime.h>
#include <cuda_bf16.h>
#include <cstdint>
#include <math.h>

#define NN 8
#define BB 64
#define TT 256
#define INP 64
#define HH 512
#define GG 2048
#define MM 512
#define OO 7

__device__ float g_z[(size_t)BB*TT*HH];
__device__ float g_xg0[(size_t)TT*NN*BB*GG];
__device__ float g_h0[2][NN*BB*HH];
__device__ float g_h1[2][NN*BB*HH];
__device__ float g_c0[NN*BB*HH];
__device__ float g_c1[NN*BB*HH];
__device__ float g_y[(size_t)NN*BB*TT*HH];
__device__ float g_hid[(size_t)NN*BB*TT*MM];
__device__ unsigned g_barc, g_barg;

__device__ __forceinline__ float sigf(float x){return 1.0f/(1.0f+expf(-x));}
#define SWZ(row,kw) (((row)<<4)+((kw)^((((row)>>1)&3)<<2)))

__device__ __forceinline__ void split2(float x,float y,unsigned&hi,unsigned&lo){
    __nv_bfloat162 h=__floats2bfloat162_rn(x,y);
    float hx=__low2float(h), hy=__high2float(h);
    __nv_bfloat162 l=__floats2bfloat162_rn(x-hx,y-hy);
    hi=*(unsigned*)&h; lo=*(unsigned*)&l;
}
__device__ __forceinline__ void st_split(unsigned*sh,unsigned*sl,int row,int kw,float4 v){
    unsigned h0,h1,l0,l1;
    split2(v.x,v.y,h0,l0); split2(v.z,v.w,h1,l1);
    int i=SWZ(row,kw);
    *(uint2*)&sh[i]=make_uint2(h0,h1);
    *(uint2*)&sl[i]=make_uint2(l0,l1);
}
__device__ __forceinline__ void mmab(float(&d)[4],const unsigned(&a)[4],unsigned b0,unsigned b1){
    asm volatile("mma.sync.aligned.m16n8k16.row.col.f32.bf16.bf16.f32 "
        "{%0,%1,%2,%3},{%4,%5,%6,%7},{%8,%9},{%0,%1,%2,%3};"
        :"+f"(d[0]),"+f"(d[1]),"+f"(d[2]),"+f"(d[3])
        :"r"(a[0]),"r"(a[1]),"r"(a[2]),"r"(a[3]),"r"(b0),"r"(b1));
}

__global__ void k_init(){
    int i=blockIdx.x*blockDim.x+threadIdx.x, st=gridDim.x*blockDim.x;
    for(int j=i;j<NN*BB*HH;j+=st){g_h0[0][j]=0.f;g_h1[0][j]=0.f;g_c0[j]=0.f;g_c1[j]=0.f;}
    if(i==0){g_barc=0u;g_barg=0u;}
}

// Tensor-core GEMM core: rows = MT*32 (A), 128 cols (B rows), fp32 in, bf16-split 3-term.
// REMAP: B row index = (col&3)*HH + hh0 + (col>>2)  (gate-interleaved recurrent cols)
template<int MT, bool REMAP>
__device__ __forceinline__ void gemmTC(const float* __restrict__ A,int lda,
                                       const float* __restrict__ B,int ldb,
                                       int K,int hh0,unsigned* sm,float(&C)[MT][4][4]){
    unsigned* sAh=sm; unsigned* sAl=sm+MT*512;
    unsigned* sBh=sm+MT*1024; unsigned* sBl=sm+MT*1024+2048;
    const int tid=threadIdx.x, lane=tid&31, w=tid>>5;
    const int wm=w>>2, wn=w&3, g=lane>>2, cq=lane&3;
    float4 ra[MT], rb[4];
#pragma unroll
    for(int j=0;j<MT;j++){int v=tid+j*256; ra[j]=*(const float4*)(A+(size_t)(v>>3)*lda+(v&7)*4);}
#pragma unroll
    for(int j=0;j<4;j++){int v=tid+j*256;int col=v>>3;
        int br=REMAP?((col&3)*HH+hh0+(col>>2)):col;
        rb[j]=*(const float4*)(B+(size_t)br*ldb+(v&7)*4);}
    const int NC=K>>5;
    for(int c=0;c<NC;c++){
#pragma unroll
        for(int j=0;j<MT;j++){int v=tid+j*256; st_split(sAh,sAl,v>>3,(v&7)*2,ra[j]);}
#pragma unroll
        for(int j=0;j<4;j++){int v=tid+j*256; st_split(sBh,sBl,v>>3,(v&7)*2,rb[j]);}
        __syncthreads();
        if(c+1<NC){int k0=(c+1)*32;
#pragma unroll
            for(int j=0;j<MT;j++){int v=tid+j*256; ra[j]=*(const float4*)(A+(size_t)(v>>3)*lda+k0+(v&7)*4);}
#pragma unroll
            for(int j=0;j<4;j++){int v=tid+j*256;int col=v>>3;
                int br=REMAP?((col&3)*HH+hh0+(col>>2)):col;
                rb[j]=*(const float4*)(B+(size_t)br*ldb+k0+(v&7)*4);}
        }
#pragma unroll
        for(int s=0;s<2;s++){
            unsigned ah[MT][4], al[MT][4];
#pragma unroll
            for(int mt=0;mt<MT;mt++){
                int r=wm*(MT*16)+mt*16+g;
                int ia=(8*s+cq)^(((r>>1)&3)<<2);
                ah[mt][0]=sAh[r*16+ia]; ah[mt][1]=sAh[(r+8)*16+ia];
                ah[mt][2]=sAh[r*16+(ia^4)]; ah[mt][3]=sAh[(r+8)*16+(ia^4)];
                al[mt][0]=sAl[r*16+ia]; al[mt][1]=sAl[(r+8)*16+ia];
                al[mt][2]=sAl[r*16+(ia^4)]; al[mt][3]=sAl[(r+8)*16+(ia^4)];
            }
#pragma unroll
            for(int nt=0;nt<4;nt++){
                int cb=wn*32+nt*8+g;
                int ib=(8*s+cq)^(((cb>>1)&3)<<2);
                unsigned bh0=sBh[cb*16+ib], bh1=sBh[cb*16+(ib^4)];
                unsigned bl0=sBl[cb*16+ib], bl1=sBl[cb*16+(ib^4)];
#pragma unroll
                for(int mt=0;mt<MT;mt++){
                    mmab(C[mt][nt],ah[mt],bh0,bh1);
                    mmab(C[mt][nt],al[mt],bh0,bh1);
                    mmab(C[mt][nt],ah[mt],bl0,bl1);
                }
            }
        }
        __syncthreads();
    }
}

// ---------- input: z = leaky(x @ Win^T + bin)*10 ----------
__global__ void __launch_bounds__(256) k_input(const float* __restrict__ x,
        const float* __restrict__ Win,const float* __restrict__ bin_){
    __shared__ unsigned sm[8192];
    float C[4][4][4]={};
    gemmTC<4,false>(x+(size_t)blockIdx.x*128*INP,INP,Win+(size_t)blockIdx.y*128*INP,INP,INP,0,sm,C);
    const int lane=threadIdx.x&31,w=threadIdx.x>>5,wm=w>>2,wn=w&3,g=lane>>2,cq=lane&3;
#pragma unroll
    for(int mt=0;mt<4;mt++)
#pragma unroll
    for(int nt=0;nt<4;nt++){
        int col=blockIdx.y*128+wn*32+nt*8+cq*2;
        float b0=bin_[col],b1=bin_[col+1];
#pragma unroll
        for(int hh=0;hh<2;hh++){
            int row=blockIdx.x*128+wm*64+mt*16+g+hh*8;
            float vx=C[mt][nt][hh*2]+b0, vy=C[mt][nt][hh*2+1]+b1;
            float2 o; o.x=(vx>0.f?vx:0.2f*vx)*10.f; o.y=(vy>0.f?vy:0.2f*vy)*10.f;
            *(float2*)&g_z[(size_t)row*HH+col]=o;
        }
    }
}

// ---------- xg0: [t][n][b][gc] = z @ W_ih0^T + b_ih0 + b_hh0 ----------
__global__ void __launch_bounds__(256) k_xg0(const float* __restrict__ W_ih0,
        const float* __restrict__ b_ih0,const float* __restrict__ b_hh0){
    __shared__ unsigned sm[8192];
    int n=blockIdx.z;
    float C[4][4][4]={};
    gemmTC<4,false>(g_z+(size_t)blockIdx.x*128*HH,HH,
                    W_ih0+((size_t)n*GG+(size_t)blockIdx.y*128)*HH,HH,HH,0,sm,C);
    const int lane=threadIdx.x&31,w=threadIdx.x>>5,wm=w>>2,wn=w&3,g=lane>>2,cq=lane&3;
#pragma unroll
    for(int mt=0;mt<4;mt++)
#pragma unroll
    for(int nt=0;nt<4;nt++){
        int gc=blockIdx.y*128+wn*32+nt*8+cq*2;
        float b0=b_ih0[(size_t)n*GG+gc]+b_hh0[(size_t)n*GG+gc];
        float b1=b_ih0[(size_t)n*GG+gc+1]+b_hh0[(size_t)n*GG+gc+1];
#pragma unroll
        for(int hh=0;hh<2;hh++){
            int grow=blockIdx.x*128+wm*64+mt*16+g+hh*8;
            int b=grow>>8, t=grow&255;
            float2 o; o.x=C[mt][nt][hh*2]+b0; o.y=C[mt][nt][hh*2+1]+b1;
            *(float2*)&g_xg0[(((size_t)t*NN+n)*BB+b)*GG+gc]=o;
        }
    }
}

// ---------- heads1: hid = leaky(y @ Wh1^T + bh1) ----------
__global__ void __launch_bounds__(256) k_heads1(const float* __restrict__ Wh1,
        const float* __restrict__ bh1){
    __shared__ unsigned sm[8192];
    int n=blockIdx.z;
    float C[4][4][4]={};
    gemmTC<4,false>(g_y+((size_t)n*BB*TT+(size_t)blockIdx.x*128)*HH,HH,
                    Wh1+((size_t)n*MM+(size_t)blockIdx.y*128)*HH,HH,HH,0,sm,C);
    const int lane=threadIdx.x&31,w=threadIdx.x>>5,wm=w>>2,wn=w&3,g=lane>>2,cq=lane&3;
#pragma unroll
    for(int mt=0;mt<4;mt++)
#pragma unroll
    for(int nt=0;nt<4;nt++){
        int m=blockIdx.y*128+wn*32+nt*8+cq*2;
        float b0=bh1[(size_t)n*MM+m],b1=bh1[(size_t)n*MM+m+1];
#pragma unroll
        for(int hh=0;hh<2;hh++){
            int row=blockIdx.x*128+wm*64+mt*16+g+hh*8;
            float vx=C[mt][nt][hh*2]+b0, vy=C[mt][nt][hh*2+1]+b1;
            float2 o; o.x=(vx>0.f?vx:0.2f*vx); o.y=(vy>0.f?vy:0.2f*vy);
            *(float2*)&g_hid[((size_t)n*BB*TT+row)*MM+m]=o;
        }
    }
}

__device__ __forceinline__ void stage_rec(float(&C)[2][4][4],float* sC){
    const int lane=threadIdx.x&31,w=threadIdx.x>>5,wm=w>>2,wn=w&3,g=lane>>2,cq=lane&3;
#pragma unroll
    for(int mt=0;mt<2;mt++){
        int r=wm*32+mt*16+g;
#pragma unroll
        for(int nt=0;nt<4;nt++){
            int col=wn*32+nt*8+cq*2;
            *(float2*)&sC[r*132+col]=make_float2(C[mt][nt][0],C[mt][nt][1]);
            *(float2*)&sC[(r+8)*132+col]=make_float2(C[mt][nt][2],C[mt][nt][3]);
        }
    }
}

__device__ __forceinline__ void grid_bar(unsigned nb){
    __syncthreads();
    if(threadIdx.x==0){
        __threadfence();
        unsigned gen=atomicAdd(&g_barg,0u);
        unsigned t=atomicAdd(&g_barc,1u);
        if(t==nb-1u){atomicExch(&g_barc,0u);__threadfence();atomicAdd(&g_barg,1u);}
        else{while(atomicAdd(&g_barg,0u)==gen){__nanosleep(64);}}
        __threadfence();
    }
    __syncthreads();
}

// ---------- persistent recurrent kernel: 128 blocks = (n, 32-hidden col tile) ----------
__global__ void __launch_bounds__(256) k_rec(const float* __restrict__ W_hh0,
        const float* __restrict__ W_ih1,const float* __restrict__ W_hh1,
        const float* __restrict__ b_ih1,const float* __restrict__ b_hh1){
    __shared__ unsigned sm[8448];
    float* sC=(float*)sm;
    const int tid=threadIdx.x;
    const int n=blockIdx.x>>4, ct=blockIdx.x&15, hh0=ct*32;
    const unsigned nb=gridDim.x;
    const float* Whh0n=W_hh0+(size_t)n*GG*HH;
    const float* Wih1n=W_ih1+(size_t)n*GG*HH;
    const float* Whh1n=W_hh1+(size_t)n*GG*HH;
    const float* bi1=b_ih1+(size_t)n*GG;
    const float* bh1g=b_hh1+(size_t)n*GG;
    const size_t st=(size_t)n*BB*HH;
    const int b=tid>>2, q=tid&3;

    for(int t=0;t<=TT;t++){
        int p=t&1;
        if(t>0){ // layer 1 for step t-1: h0 input = g_h0[p], prev h1 = g_h1[p^1]
            float C[2][4][4]={};
            gemmTC<2,true>(g_h0[p]+st,HH,Wih1n,HH,HH,hh0,sm,C);
            gemmTC<2,true>(g_h1[p^1]+st,HH,Whh1n,HH,HH,hh0,sm,C);
            stage_rec(C,sC);
            __syncthreads();
            size_t hb=st+(size_t)b*HH+hh0;
#pragma unroll
            for(int k=0;k<8;k++){
                int hl=q*8+k, h=hh0+hl;
                float pi=sC[b*132+hl*4+0]+bi1[h]+bh1g[h];
                float pf=sC[b*132+hl*4+1]+bi1[HH+h]+bh1g[HH+h];
                float pg=sC[b*132+hl*4+2]+bi1[2*HH+h]+bh1g[2*HH+h];
                float po=sC[b*132+hl*4+3]+bi1[3*HH+h]+bh1g[3*HH+h];
                float cn=sigf(pf)*g_c1[hb+hl]+sigf(pi)*tanhf(pg);
                float hn=sigf(po)*tanhf(cn);
                g_c1[hb+hl]=cn; g_h1[p][hb+hl]=hn;
                g_y[(((size_t)n*BB+b)*TT+(t-1))*HH+h]=hn;
            }
            __syncthreads();
        }
        if(t<TT){ // layer 0 for step t: prev h0 = g_h0[p]
            float C[2][4][4]={};
            gemmTC<2,true>(g_h0[p]+st,HH,Whh0n,HH,HH,hh0,sm,C);
            stage_rec(C,sC);
            __syncthreads();
            const float* xgb=g_xg0+(((size_t)t*NN+n)*BB+b)*GG;
            size_t hb=st+(size_t)b*HH+hh0;
#pragma unroll
            for(int k=0;k<8;k++){
                int hl=q*8+k, h=hh0+hl;
                float pi=sC[b*132+hl*4+0]+xgb[h];
                float pf=sC[b*132+hl*4+1]+xgb[HH+h];
                float pg=sC[b*132+hl*4+2]+xgb[2*HH+h];
                float po=sC[b*132+hl*4+3]+xgb[3*HH+h];
                float cn=sigf(pf)*g_c0[hb+hl]+sigf(pi)*tanhf(pg);
                float hn=sigf(po)*tanhf(cn);
                g_c0[hb+hl]=cn; g_h0[p^1][hb+hl]=hn;
            }
            __syncthreads();
        }
        grid_bar(nb);
    }
}

// ---------- heads2: out = hid @ Wh2^T + bh2 ----------
__global__ void __launch_bounds__(256) k_heads2(const float* __restrict__ Wh2,
        const float* __restrict__ bh2,float* __restrict__ out){
    int gw=(blockIdx.x*blockDim.x+threadIdx.x)>>5;
    int lane=threadIdx.x&31;
    if(gw>=NN*BB*TT) return;
    int n=gw>>14;
    const float* hrow=g_hid+(size_t)gw*MM;
    float hv[16];
#pragma unroll
    for(int qq=0;qq<4;qq++){
        float4 v=*(const float4*)(hrow+lane*16+qq*4);
        hv[qq*4]=v.x;hv[qq*4+1]=v.y;hv[qq*4+2]=v.z;hv[qq*4+3]=v.w;
    }
    const float* W=Wh2+(size_t)n*OO*MM;
#pragma unroll
    for(int o=0;o<OO;o++){
        const float4* w4=(const float4*)(W+(size_t)o*MM+lane*16);
        float s=0.f;
#pragma unroll
        for(int qq=0;qq<4;qq++){
            float4 wv=w4[qq];
            s+=hv[qq*4]*wv.x+hv[qq*4+1]*wv.y+hv[qq*4+2]*wv.z+hv[qq*4+3]*wv.w;
        }
#pragma unroll
        for(int off=16;off>0;off>>=1) s+=__shfl_xor_sync(0xFFFFFFFFu,s,off);
        if(lane==0) out[(size_t)gw*OO+o]=s+bh2[(size_t)n*OO+o];
    }
}

extern "C" void kernel_launch(void* const* d_in, const int* in_sizes, int n_in,
                              void* d_out, int out_size){
    const float* x=(const float*)d_in[0];
    const float* Win=(const float*)d_in[1];
    const float* bin_=(const float*)d_in[2];
    const float* W_ih0=(const float*)d_in[3];
    const float* W_hh0=(const float*)d_in[4];
    const float* b_ih0=(const float*)d_in[5];
    const float* b_hh0=(const float*)d_in[6];
    const float* W_ih1=(const float*)d_in[7];
    const float* W_hh1=(const float*)d_in[8];
    const float* b_ih1=(const float*)d_in[9];
    const float* b_hh1=(const float*)d_in[10];
    const float* Wh1=(const float*)d_in[11];
    const float* bh1=(const float*)d_in[12];
    const float* Wh2=(const float*)d_in[13];
    const float* bh2=(const float*)d_in[14];
    float* out=(float*)d_out;

    k_init<<<256,256>>>();
    k_input<<<dim3(128,4),256>>>(x,Win,bin_);
    k_xg0<<<dim3(128,16,NN),256>>>(W_ih0,b_ih0,b_hh0);
    k_rec<<<128,256>>>(W_hh0,W_ih1,W_hh1,b_ih1,b_hh1);
    k_heads1<<<dim3(128,4,NN),256>>>(Wh1,bh1);
    k_heads2<<<(NN*BB*TT)/8,256>>>(Wh2,bh2,out);
}

// round 8
// speedup vs baseline: 2.8056x; 1.1017x over previous
#include <cuda_runtime.h>
#include <cuda_bf16.h>
#include <cstdint>
#include <math.h>

#define NN 8
#define BB 64
#define TT 256
#define INP 64
#define HH 512
#define GG 2048
#define MM 512
#define OO 7
typedef __nv_bfloat16 bf;

// ---------------- globals ----------------
__device__ __align__(16) bf g_xh[(size_t)BB*TT*INP], g_xl[(size_t)BB*TT*INP];
__device__ __align__(16) bf g_winh[HH*INP], g_winl[HH*INP];
__device__ __align__(16) bf g_zh[(size_t)BB*TT*HH], g_zl[(size_t)BB*TT*HH];
__device__ __align__(16) bf g_wih0h[(size_t)NN*GG*HH], g_wih0l[(size_t)NN*GG*HH];
__device__ __align__(16) bf g_wh1h[(size_t)NN*MM*HH], g_wh1l[(size_t)NN*MM*HH];
__device__ __align__(16) bf g_rwh[(size_t)3*NN*GG*HH], g_rwl[(size_t)3*NN*GG*HH];
__device__ __align__(16) bf g_h0h[2][NN*BB*HH], g_h0l[2][NN*BB*HH];
__device__ __align__(16) bf g_h1h[2][NN*BB*HH], g_h1l[2][NN*BB*HH];
__device__ float g_c0[NN*BB*HH], g_c1[NN*BB*HH];
__device__ __align__(16) bf g_yh[(size_t)NN*BB*TT*HH], g_yl[(size_t)NN*BB*TT*HH];
__device__ float g_xg0[(size_t)TT*NN*BB*GG];
__device__ float g_hid[(size_t)NN*BB*TT*MM];
__device__ unsigned g_barc, g_barg;

__device__ __forceinline__ float sigf(float x){return 1.0f/(1.0f+expf(-x));}
#define SWZ(row,kw) (((row)<<4)+((kw)^((((row)>>1)&3)<<2)))

__device__ __forceinline__ void split2(float x,float y,unsigned&hi,unsigned&lo){
    __nv_bfloat162 h=__floats2bfloat162_rn(x,y);
    float hx=__low2float(h), hy=__high2float(h);
    __nv_bfloat162 l=__floats2bfloat162_rn(x-hx,y-hy);
    hi=*(unsigned*)&h; lo=*(unsigned*)&l;
}
__device__ __forceinline__ void mmab(float(&d)[4],const unsigned(&a)[4],unsigned b0,unsigned b1){
    asm volatile("mma.sync.aligned.m16n8k16.row.col.f32.bf16.bf16.f32 "
        "{%0,%1,%2,%3},{%4,%5,%6,%7},{%8,%9},{%0,%1,%2,%3};"
        :"+f"(d[0]),"+f"(d[1]),"+f"(d[2]),"+f"(d[3])
        :"r"(a[0]),"r"(a[1]),"r"(a[2]),"r"(a[3]),"r"(b0),"r"(b1));
}

__global__ void k_init(){
    int i=blockIdx.x*blockDim.x+threadIdx.x, st=gridDim.x*blockDim.x;
    for(int j=i;j<NN*BB*HH;j+=st){
        ((unsigned short*)g_h0h[0])[j]=0;((unsigned short*)g_h0l[0])[j]=0;
        ((unsigned short*)g_h1h[0])[j]=0;((unsigned short*)g_h1l[0])[j]=0;
        g_c0[j]=0.f;g_c1[j]=0.f;
    }
    if(i==0){g_barc=0u;g_barg=0u;}
}

// generic fp32 -> bf16 hi/lo split
__global__ void k_split2(const float* __restrict__ s, bf* dh, bf* dl, int cnt){
    int i=blockIdx.x*blockDim.x+threadIdx.x;
    if(i<cnt){float v=s[i]; bf h=__float2bfloat16(v);
        dh[i]=h; dl[i]=__float2bfloat16(v-__bfloat162float(h));}
}

// recurrent weights: remap to [w][n][ct(16)][c(128)][k], c = hidden_local*4+gate
__global__ void k_split_rec(const float* __restrict__ W0,const float* __restrict__ W1,
                            const float* __restrict__ W2){
    size_t idx=(size_t)blockIdx.x*blockDim.x+threadIdx.x;
    if(idx>=(size_t)3*NN*GG*HH) return;
    int k=idx&511; int c=(int)((idx>>9)&127); int ct=(int)((idx>>16)&15);
    int n=(int)((idx>>20)&7); int w=(int)(idx>>23);
    int hidden=ct*32+(c>>2), gate=c&3;
    const float* W=(w==0)?W0:((w==1)?W1:W2);
    float v=W[((size_t)n*GG+gate*HH+hidden)*HH+k];
    bf h=__float2bfloat16(v);
    g_rwh[idx]=h; g_rwl[idx]=__float2bfloat16(v-__bfloat162float(h));
}

// ============ parallel GEMM: 128x128 tile, pre-split bf16 in ============
__device__ __forceinline__ void gemmP(const bf* __restrict__ Ah,const bf* __restrict__ Al,int lda,
        const bf* __restrict__ Bh,const bf* __restrict__ Bl,int ldb,int K,
        unsigned* sm,float(&C)[4][4][4]){
    unsigned* sAh=sm; unsigned* sAl=sm+2048; unsigned* sBh=sm+4096; unsigned* sBl=sm+6144;
    const int tid=threadIdx.x,lane=tid&31,w=tid>>5,wm=w>>2,wn=w&3,g=lane>>2,cq=lane&3;
    for(int k0=0;k0<K;k0+=32){
#pragma unroll
        for(int j=0;j<2;j++){
            int v=tid+j*256,row=v>>2,e8=(v&3)*8,kw=(v&3)*4;
            *(uint4*)&sAh[SWZ(row,kw)]=*(const uint4*)(Ah+(size_t)row*lda+k0+e8);
            *(uint4*)&sAl[SWZ(row,kw)]=*(const uint4*)(Al+(size_t)row*lda+k0+e8);
            *(uint4*)&sBh[SWZ(row,kw)]=*(const uint4*)(Bh+(size_t)row*ldb+k0+e8);
            *(uint4*)&sBl[SWZ(row,kw)]=*(const uint4*)(Bl+(size_t)row*ldb+k0+e8);
        }
        __syncthreads();
#pragma unroll
        for(int s=0;s<2;s++){
            unsigned ah[4][4],al[4][4];
#pragma unroll
            for(int mt=0;mt<4;mt++){
                int r=wm*64+mt*16+g;
                int ia=(8*s+cq)^(((r>>1)&3)<<2);
                ah[mt][0]=sAh[r*16+ia]; ah[mt][1]=sAh[(r+8)*16+ia];
                ah[mt][2]=sAh[r*16+(ia^4)]; ah[mt][3]=sAh[(r+8)*16+(ia^4)];
                al[mt][0]=sAl[r*16+ia]; al[mt][1]=sAl[(r+8)*16+ia];
                al[mt][2]=sAl[r*16+(ia^4)]; al[mt][3]=sAl[(r+8)*16+(ia^4)];
            }
#pragma unroll
            for(int nt=0;nt<4;nt++){
                int cb=wn*32+nt*8+g;
                int ib=(8*s+cq)^(((cb>>1)&3)<<2);
                unsigned bh0=sBh[cb*16+ib],bh1=sBh[cb*16+(ib^4)];
                unsigned bl0=sBl[cb*16+ib],bl1=sBl[cb*16+(ib^4)];
#pragma unroll
                for(int mt=0;mt<4;mt++){
                    mmab(C[mt][nt],ah[mt],bh0,bh1);
                    mmab(C[mt][nt],al[mt],bh0,bh1);
                    mmab(C[mt][nt],ah[mt],bl0,bl1);
                }
            }
        }
        __syncthreads();
    }
}

// ============ recurrent GEMM: 64x128 tile, prefetched, K=512 ============
__device__ __forceinline__ void gemmR(const bf* __restrict__ Ah,const bf* __restrict__ Al,
        const bf* __restrict__ Bh,const bf* __restrict__ Bl,
        unsigned* sm,float(&C)[2][4][4]){
    unsigned* sAh=sm; unsigned* sAl=sm+1024; unsigned* sBh=sm+2048; unsigned* sBl=sm+4096;
    const int tid=threadIdx.x,lane=tid&31,w=tid>>5,wm=w>>2,wn=w&3,g=lane>>2,cq=lane&3;
    const int ar=tid>>2, a8=(tid&3)*8, akw=(tid&3)*4;
    uint4 pah,pal,pbh[2],pbl[2];
    pah=*(const uint4*)(Ah+(size_t)ar*HH+a8);
    pal=*(const uint4*)(Al+(size_t)ar*HH+a8);
#pragma unroll
    for(int j=0;j<2;j++){int v=tid+j*256,row=v>>2,e8=(v&3)*8;
        pbh[j]=*(const uint4*)(Bh+(size_t)row*HH+e8);
        pbl[j]=*(const uint4*)(Bl+(size_t)row*HH+e8);}
    for(int c=0;c<16;c++){
        *(uint4*)&sAh[SWZ(ar,akw)]=pah;
        *(uint4*)&sAl[SWZ(ar,akw)]=pal;
#pragma unroll
        for(int j=0;j<2;j++){int v=tid+j*256,row=v>>2,kw=(v&3)*4;
            *(uint4*)&sBh[SWZ(row,kw)]=pbh[j];
            *(uint4*)&sBl[SWZ(row,kw)]=pbl[j];}
        __syncthreads();
        if(c<15){int k0=(c+1)*32;
            pah=*(const uint4*)(Ah+(size_t)ar*HH+k0+a8);
            pal=*(const uint4*)(Al+(size_t)ar*HH+k0+a8);
#pragma unroll
            for(int j=0;j<2;j++){int v=tid+j*256,row=v>>2,e8=(v&3)*8;
                pbh[j]=*(const uint4*)(Bh+(size_t)row*HH+k0+e8);
                pbl[j]=*(const uint4*)(Bl+(size_t)row*HH+k0+e8);}
        }
#pragma unroll
        for(int s=0;s<2;s++){
            unsigned ah[2][4],al[2][4];
#pragma unroll
            for(int mt=0;mt<2;mt++){
                int r=wm*32+mt*16+g;
                int ia=(8*s+cq)^(((r>>1)&3)<<2);
                ah[mt][0]=sAh[r*16+ia]; ah[mt][1]=sAh[(r+8)*16+ia];
                ah[mt][2]=sAh[r*16+(ia^4)]; ah[mt][3]=sAh[(r+8)*16+(ia^4)];
                al[mt][0]=sAl[r*16+ia]; al[mt][1]=sAl[(r+8)*16+ia];
                al[mt][2]=sAl[r*16+(ia^4)]; al[mt][3]=sAl[(r+8)*16+(ia^4)];
            }
#pragma unroll
            for(int nt=0;nt<4;nt++){
                int cb=wn*32+nt*8+g;
                int ib=(8*s+cq)^(((cb>>1)&3)<<2);
                unsigned bh0=sBh[cb*16+ib],bh1=sBh[cb*16+(ib^4)];
                unsigned bl0=sBl[cb*16+ib],bl1=sBl[cb*16+(ib^4)];
#pragma unroll
                for(int mt=0;mt<2;mt++){
                    mmab(C[mt][nt],ah[mt],bh0,bh1);
                    mmab(C[mt][nt],al[mt],bh0,bh1);
                    mmab(C[mt][nt],ah[mt],bl0,bl1);
                }
            }
        }
        __syncthreads();
    }
}

// ---------- input: z = leaky(x @ Win^T + bin)*10, stored split ----------
__global__ void __launch_bounds__(256,2) k_input(const float* __restrict__ bin_){
    __shared__ unsigned sm[8192];
    float C[4][4][4]={};
    gemmP(g_xh+(size_t)blockIdx.x*128*INP, g_xl+(size_t)blockIdx.x*128*INP, INP,
          g_winh+(size_t)blockIdx.y*128*INP, g_winl+(size_t)blockIdx.y*128*INP, INP, INP, sm, C);
    const int lane=threadIdx.x&31,w=threadIdx.x>>5,wm=w>>2,wn=w&3,g=lane>>2,cq=lane&3;
#pragma unroll
    for(int mt=0;mt<4;mt++)
#pragma unroll
    for(int nt=0;nt<4;nt++){
        int col=blockIdx.y*128+wn*32+nt*8+cq*2;
        float b0=bin_[col],b1=bin_[col+1];
#pragma unroll
        for(int hh=0;hh<2;hh++){
            int row=blockIdx.x*128+wm*64+mt*16+g+hh*8;
            float vx=C[mt][nt][hh*2]+b0, vy=C[mt][nt][hh*2+1]+b1;
            vx=(vx>0.f?vx:0.2f*vx)*10.f; vy=(vy>0.f?vy:0.2f*vy)*10.f;
            unsigned hi,lo; split2(vx,vy,hi,lo);
            *(unsigned*)&g_zh[(size_t)row*HH+col]=hi;
            *(unsigned*)&g_zl[(size_t)row*HH+col]=lo;
        }
    }
}

// ---------- xg0 ----------
__global__ void __launch_bounds__(256,2) k_xg0(const float* __restrict__ b_ih0,
        const float* __restrict__ b_hh0){
    __shared__ unsigned sm[8192];
    int n=blockIdx.z;
    float C[4][4][4]={};
    size_t bo=((size_t)n*GG+(size_t)blockIdx.y*128)*HH;
    gemmP(g_zh+(size_t)blockIdx.x*128*HH, g_zl+(size_t)blockIdx.x*128*HH, HH,
          g_wih0h+bo, g_wih0l+bo, HH, HH, sm, C);
    const int lane=threadIdx.x&31,w=threadIdx.x>>5,wm=w>>2,wn=w&3,g=lane>>2,cq=lane&3;
#pragma unroll
    for(int mt=0;mt<4;mt++)
#pragma unroll
    for(int nt=0;nt<4;nt++){
        int gc=blockIdx.y*128+wn*32+nt*8+cq*2;
        float b0=b_ih0[(size_t)n*GG+gc]+b_hh0[(size_t)n*GG+gc];
        float b1=b_ih0[(size_t)n*GG+gc+1]+b_hh0[(size_t)n*GG+gc+1];
#pragma unroll
        for(int hh=0;hh<2;hh++){
            int grow=blockIdx.x*128+wm*64+mt*16+g+hh*8;
            int b=grow>>8, t=grow&255;
            float2 o; o.x=C[mt][nt][hh*2]+b0; o.y=C[mt][nt][hh*2+1]+b1;
            *(float2*)&g_xg0[(((size_t)t*NN+n)*BB+b)*GG+gc]=o;
        }
    }
}

// ---------- heads1 ----------
__global__ void __launch_bounds__(256,2) k_heads1(const float* __restrict__ bh1){
    __shared__ unsigned sm[8192];
    int n=blockIdx.z;
    float C[4][4][4]={};
    size_t ao=(size_t)n*BB*TT*HH+(size_t)blockIdx.x*128*HH;
    size_t bo=((size_t)n*MM+(size_t)blockIdx.y*128)*HH;
    gemmP(g_yh+ao, g_yl+ao, HH, g_wh1h+bo, g_wh1l+bo, HH, HH, sm, C);
    const int lane=threadIdx.x&31,w=threadIdx.x>>5,wm=w>>2,wn=w&3,g=lane>>2,cq=lane&3;
#pragma unroll
    for(int mt=0;mt<4;mt++)
#pragma unroll
    for(int nt=0;nt<4;nt++){
        int m=blockIdx.y*128+wn*32+nt*8+cq*2;
        float b0=bh1[(size_t)n*MM+m],b1=bh1[(size_t)n*MM+m+1];
#pragma unroll
        for(int hh=0;hh<2;hh++){
            int row=blockIdx.x*128+wm*64+mt*16+g+hh*8;
            float vx=C[mt][nt][hh*2]+b0, vy=C[mt][nt][hh*2+1]+b1;
            float2 o; o.x=(vx>0.f?vx:0.2f*vx); o.y=(vy>0.f?vy:0.2f*vy);
            *(float2*)&g_hid[((size_t)n*BB*TT+row)*MM+m]=o;
        }
    }
}

__device__ __forceinline__ void stage_rec(float(&C)[2][4][4],float* sC){
    const int lane=threadIdx.x&31,w=threadIdx.x>>5,wm=w>>2,wn=w&3,g=lane>>2,cq=lane&3;
#pragma unroll
    for(int mt=0;mt<2;mt++){
        int r=wm*32+mt*16+g;
#pragma unroll
        for(int nt=0;nt<4;nt++){
            int col=wn*32+nt*8+cq*2;
            *(float2*)&sC[r*132+col]=make_float2(C[mt][nt][0],C[mt][nt][1]);
            *(float2*)&sC[(r+8)*132+col]=make_float2(C[mt][nt][2],C[mt][nt][3]);
        }
    }
}

__device__ __forceinline__ void grid_bar(unsigned nb){
    __syncthreads();
    if(threadIdx.x==0){
        __threadfence();
        unsigned gen=atomicAdd(&g_barg,0u);
        unsigned t=atomicAdd(&g_barc,1u);
        if(t==nb-1u){atomicExch(&g_barc,0u);__threadfence();atomicAdd(&g_barg,1u);}
        else{while(atomicAdd(&g_barg,0u)==gen){__nanosleep(64);}}
        __threadfence();
    }
    __syncthreads();
}

// ---------- persistent recurrent kernel: 128 blocks = (n, ct of 32 hidden) ----------
__global__ void __launch_bounds__(256) k_rec(const float* __restrict__ b_ih1,
        const float* __restrict__ b_hh1){
    __shared__ unsigned sm[8448];
    float* sC=(float*)sm;
    const int tid=threadIdx.x;
    const int n=blockIdx.x>>4, ct=blockIdx.x&15, hh0=ct*32;
    const unsigned nb=gridDim.x;
    const size_t ws=(size_t)128*HH;
    const bf* w0h=g_rwh+((size_t)(0*NN+n)*16+ct)*ws; const bf* w0l=g_rwl+((size_t)(0*NN+n)*16+ct)*ws;
    const bf* w1h=g_rwh+((size_t)(1*NN+n)*16+ct)*ws; const bf* w1l=g_rwl+((size_t)(1*NN+n)*16+ct)*ws;
    const bf* w2h=g_rwh+((size_t)(2*NN+n)*16+ct)*ws; const bf* w2l=g_rwl+((size_t)(2*NN+n)*16+ct)*ws;
    const float* bi1=b_ih1+(size_t)n*GG;
    const float* bh1g=b_hh1+(size_t)n*GG;
    const size_t st=(size_t)n*BB*HH;
    const int b=tid>>2, q=tid&3;

    for(int t=0;t<=TT;t++){
        int p=t&1;
        if(t>0){  // layer 1 for step t-1
            float C[2][4][4]={};
            gemmR(g_h0h[p]+st, g_h0l[p]+st, w1h, w1l, sm, C);
            gemmR(g_h1h[p^1]+st, g_h1l[p^1]+st, w2h, w2l, sm, C);
            stage_rec(C,sC);
            __syncthreads();
            size_t hb=st+(size_t)b*HH+hh0;
#pragma unroll
            for(int k=0;k<8;k++){
                int hl=q*8+k, h=hh0+hl;
                float pi=sC[b*132+hl*4+0]+bi1[h]+bh1g[h];
                float pf=sC[b*132+hl*4+1]+bi1[HH+h]+bh1g[HH+h];
                float pg=sC[b*132+hl*4+2]+bi1[2*HH+h]+bh1g[2*HH+h];
                float po=sC[b*132+hl*4+3]+bi1[3*HH+h]+bh1g[3*HH+h];
                float cn=sigf(pf)*g_c1[hb+hl]+sigf(pi)*tanhf(pg);
                float hn=sigf(po)*tanhf(cn);
                g_c1[hb+hl]=cn;
                bf hi=__float2bfloat16(hn);
                bf lo=__float2bfloat16(hn-__bfloat162float(hi));
                g_h1h[p][hb+hl]=hi; g_h1l[p][hb+hl]=lo;
                size_t yi=(((size_t)n*BB+b)*TT+(t-1))*HH+h;
                g_yh[yi]=hi; g_yl[yi]=lo;
            }
            __syncthreads();
        }
        if(t<TT){  // layer 0 for step t
            float C[2][4][4]={};
            gemmR(g_h0h[p]+st, g_h0l[p]+st, w0h, w0l, sm, C);
            stage_rec(C,sC);
            __syncthreads();
            const float* xgb=g_xg0+(((size_t)t*NN+n)*BB+b)*GG;
            size_t hb=st+(size_t)b*HH+hh0;
#pragma unroll
            for(int k=0;k<8;k++){
                int hl=q*8+k, h=hh0+hl;
                float pi=sC[b*132+hl*4+0]+xgb[h];
                float pf=sC[b*132+hl*4+1]+xgb[HH+h];
                float pg=sC[b*132+hl*4+2]+xgb[2*HH+h];
                float po=sC[b*132+hl*4+3]+xgb[3*HH+h];
                float cn=sigf(pf)*g_c0[hb+hl]+sigf(pi)*tanhf(pg);
                float hn=sigf(po)*tanhf(cn);
                g_c0[hb+hl]=cn;
                bf hi=__float2bfloat16(hn);
                g_h0h[p^1][hb+hl]=hi;
                g_h0l[p^1][hb+hl]=__float2bfloat16(hn-__bfloat162float(hi));
            }
            __syncthreads();
        }
        grid_bar(nb);
    }
}

// ---------- heads2 ----------
__global__ void __launch_bounds__(256) k_heads2(const float* __restrict__ Wh2,
        const float* __restrict__ bh2,float* __restrict__ out){
    int gw=(blockIdx.x*blockDim.x+threadIdx.x)>>5;
    int lane=threadIdx.x&31;
    if(gw>=NN*BB*TT) return;
    int n=gw>>14;
    const float* hrow=g_hid+(size_t)gw*MM;
    float hv[16];
#pragma unroll
    for(int qq=0;qq<4;qq++){
        float4 v=*(const float4*)(hrow+lane*16+qq*4);
        hv[qq*4]=v.x;hv[qq*4+1]=v.y;hv[qq*4+2]=v.z;hv[qq*4+3]=v.w;
    }
    const float* W=Wh2+(size_t)n*OO*MM;
#pragma unroll
    for(int o=0;o<OO;o++){
        const float4* w4=(const float4*)(W+(size_t)o*MM+lane*16);
        float s=0.f;
#pragma unroll
        for(int qq=0;qq<4;qq++){
            float4 wv=w4[qq];
            s+=hv[qq*4]*wv.x+hv[qq*4+1]*wv.y+hv[qq*4+2]*wv.z+hv[qq*4+3]*wv.w;
        }
#pragma unroll
        for(int off=16;off>0;off>>=1) s+=__shfl_xor_sync(0xFFFFFFFFu,s,off);
        if(lane==0) out[(size_t)gw*OO+o]=s+bh2[(size_t)n*OO+o];
    }
}

extern "C" void kernel_launch(void* const* d_in, const int* in_sizes, int n_in,
                              void* d_out, int out_size){
    const float* x=(const float*)d_in[0];
    const float* Win=(const float*)d_in[1];
    const float* bin_=(const float*)d_in[2];
    const float* W_ih0=(const float*)d_in[3];
    const float* W_hh0=(const float*)d_in[4];
    const float* b_ih0=(const float*)d_in[5];
    const float* b_hh0=(const float*)d_in[6];
    const float* W_ih1=(const float*)d_in[7];
    const float* W_hh1=(const float*)d_in[8];
    const float* b_ih1=(const float*)d_in[9];
    const float* b_hh1=(const float*)d_in[10];
    const float* Wh1=(const float*)d_in[11];
    const float* bh1=(const float*)d_in[12];
    const float* Wh2=(const float*)d_in[13];
    const float* bh2=(const float*)d_in[14];
    float* out=(float*)d_out;

    k_init<<<256,256>>>();
    bf *xh, *xl, *winh, *winl, *wih0h, *wih0l, *wh1h, *wh1l;
    cudaGetSymbolAddress((void**)&xh, g_xh);   cudaGetSymbolAddress((void**)&xl, g_xl);
    cudaGetSymbolAddress((void**)&winh, g_winh); cudaGetSymbolAddress((void**)&winl, g_winl);
    cudaGetSymbolAddress((void**)&wih0h, g_wih0h); cudaGetSymbolAddress((void**)&wih0l, g_wih0l);
    cudaGetSymbolAddress((void**)&wh1h, g_wh1h); cudaGetSymbolAddress((void**)&wh1l, g_wh1l);
    k_split2<<<(BB*TT*INP+255)/256,256>>>(x, xh, xl, BB*TT*INP);
    k_split2<<<(HH*INP+255)/256,256>>>(Win, winh, winl, HH*INP);
    k_split2<<<(NN*GG*HH+255)/256,256>>>(W_ih0, wih0h, wih0l, NN*GG*HH);
    k_split2<<<(NN*MM*HH+255)/256,256>>>(Wh1, wh1h, wh1l, NN*MM*HH);
    k_split_rec<<<(int)(((size_t)3*NN*GG*HH+255)/256),256>>>(W_hh0, W_ih1, W_hh1);

    k_input<<<dim3(128,4),256>>>(bin_);
    k_xg0<<<dim3(128,16,NN),256>>>(b_ih0,b_hh0);
    k_rec<<<128,256>>>(b_ih1,b_hh1);
    k_heads1<<<dim3(128,4,NN),256>>>(bh1);
    k_heads2<<<(NN*BB*TT)/8,256>>>(Wh2,bh2,out);
}

// round 11
// speedup vs baseline: 3.1243x; 1.1136x over previous
#include <cuda_runtime.h>
#include <cuda_bf16.h>
#include <cuda_fp16.h>
#include <cstdint>
#include <math.h>

#define NN 8
#define BB 64
#define TT 256
#define INP 64
#define HH 512
#define GG 2048
#define MM 512
#define OO 7
typedef __nv_bfloat16 bf;
typedef __half hf;

// ---------------- globals ----------------
__device__ __align__(16) bf g_xh[(size_t)BB*TT*INP], g_xl[(size_t)BB*TT*INP];
__device__ __align__(16) bf g_winh[HH*INP], g_winl[HH*INP];
__device__ __align__(16) bf g_zh[(size_t)BB*TT*HH], g_zl[(size_t)BB*TT*HH];
__device__ __align__(16) bf g_wih0h[(size_t)NN*GG*HH], g_wih0l[(size_t)NN*GG*HH];
__device__ __align__(16) bf g_wh1h[(size_t)NN*MM*HH], g_wh1l[(size_t)NN*MM*HH];
// recurrent weights: fp16 hi/lo, remapped [w][n][ct][c(128)][k]
__device__ __align__(16) hf g_rwh[(size_t)3*NN*GG*HH], g_rwl[(size_t)3*NN*GG*HH];
// recurrent h states: single fp16
__device__ __align__(16) hf g_h0f[2][NN*BB*HH], g_h1f[2][NN*BB*HH];
__device__ float g_c0[NN*BB*HH], g_c1[NN*BB*HH];
__device__ __align__(16) bf g_yh[(size_t)NN*BB*TT*HH], g_yl[(size_t)NN*BB*TT*HH];
__device__ float g_xg0[(size_t)TT*NN*BB*GG];
__device__ float g_hid[(size_t)NN*BB*TT*MM];
__device__ unsigned g_barc, g_barg;

__device__ __forceinline__ float sigf(float x){return 1.0f/(1.0f+expf(-x));}
#define SWZ(row,kw) (((row)<<4)+((kw)^((((row)>>1)&3)<<2)))

__device__ __forceinline__ void split2(float x,float y,unsigned&hi,unsigned&lo){
    __nv_bfloat162 h=__floats2bfloat162_rn(x,y);
    float hx=__low2float(h), hy=__high2float(h);
    __nv_bfloat162 l=__floats2bfloat162_rn(x-hx,y-hy);
    hi=*(unsigned*)&h; lo=*(unsigned*)&l;
}
__device__ __forceinline__ void mmab(float(&d)[4],const unsigned(&a)[4],unsigned b0,unsigned b1){
    asm volatile("mma.sync.aligned.m16n8k16.row.col.f32.bf16.bf16.f32 "
        "{%0,%1,%2,%3},{%4,%5,%6,%7},{%8,%9},{%0,%1,%2,%3};"
        :"+f"(d[0]),"+f"(d[1]),"+f"(d[2]),"+f"(d[3])
        :"r"(a[0]),"r"(a[1]),"r"(a[2]),"r"(a[3]),"r"(b0),"r"(b1));
}
__device__ __forceinline__ void mmah(float(&d)[4],const unsigned(&a)[4],unsigned b0,unsigned b1){
    asm volatile("mma.sync.aligned.m16n8k16.row.col.f32.f16.f16.f32 "
        "{%0,%1,%2,%3},{%4,%5,%6,%7},{%8,%9},{%0,%1,%2,%3};"
        :"+f"(d[0]),"+f"(d[1]),"+f"(d[2]),"+f"(d[3])
        :"r"(a[0]),"r"(a[1]),"r"(a[2]),"r"(a[3]),"r"(b0),"r"(b1));
}

__global__ void k_init(){
    int i=blockIdx.x*blockDim.x+threadIdx.x, st=gridDim.x*blockDim.x;
    for(int j=i;j<NN*BB*HH;j+=st){
        ((unsigned short*)g_h0f[0])[j]=0;((unsigned short*)g_h1f[0])[j]=0;
        g_c0[j]=0.f;g_c1[j]=0.f;
    }
    if(i==0){g_barc=0u;g_barg=0u;}
}

__global__ void k_split2(const float* __restrict__ s, bf* dh, bf* dl, int cnt){
    int i=blockIdx.x*blockDim.x+threadIdx.x;
    if(i<cnt){float v=s[i]; bf h=__float2bfloat16(v);
        dh[i]=h; dl[i]=__float2bfloat16(v-__bfloat162float(h));}
}

// recurrent weights remap to fp16 hi/lo: [w][n][ct(16)][c(128)][k], c = hidden_local*4+gate
__global__ void k_split_rec(const float* __restrict__ W0,const float* __restrict__ W1,
                            const float* __restrict__ W2){
    size_t idx=(size_t)blockIdx.x*blockDim.x+threadIdx.x;
    if(idx>=(size_t)3*NN*GG*HH) return;
    int k=idx&511; int c=(int)((idx>>9)&127); int ct=(int)((idx>>16)&15);
    int n=(int)((idx>>20)&7); int w=(int)(idx>>23);
    int hidden=ct*32+(c>>2), gate=c&3;
    const float* W=(w==0)?W0:((w==1)?W1:W2);
    float v=W[((size_t)n*GG+gate*HH+hidden)*HH+k];
    hf h=__float2half_rn(v);
    g_rwh[idx]=h; g_rwl[idx]=__float2half_rn(v-__half2float(h));
}

// ============ parallel mma.sync GEMM: 128x128 tile, bf16 3-term (as R8) ============
__device__ __forceinline__ void gemmP(const bf* __restrict__ Ah,const bf* __restrict__ Al,int lda,
        const bf* __restrict__ Bh,const bf* __restrict__ Bl,int ldb,int K,
        unsigned* sm,float(&C)[4][4][4]){
    unsigned* sAh=sm; unsigned* sAl=sm+2048; unsigned* sBh=sm+4096; unsigned* sBl=sm+6144;
    const int tid=threadIdx.x,lane=tid&31,w=tid>>5,wm=w>>2,wn=w&3,g=lane>>2,cq=lane&3;
    for(int k0=0;k0<K;k0+=32){
#pragma unroll
        for(int j=0;j<2;j++){
            int v=tid+j*256,row=v>>2,e8=(v&3)*8,kw=(v&3)*4;
            *(uint4*)&sAh[SWZ(row,kw)]=*(const uint4*)(Ah+(size_t)row*lda+k0+e8);
            *(uint4*)&sAl[SWZ(row,kw)]=*(const uint4*)(Al+(size_t)row*lda+k0+e8);
            *(uint4*)&sBh[SWZ(row,kw)]=*(const uint4*)(Bh+(size_t)row*ldb+k0+e8);
            *(uint4*)&sBl[SWZ(row,kw)]=*(const uint4*)(Bl+(size_t)row*ldb+k0+e8);
        }
        __syncthreads();
#pragma unroll
        for(int s=0;s<2;s++){
            unsigned ah[4][4],al[4][4];
#pragma unroll
            for(int mt=0;mt<4;mt++){
                int r=wm*64+mt*16+g;
                int ia=(8*s+cq)^(((r>>1)&3)<<2);
                ah[mt][0]=sAh[r*16+ia]; ah[mt][1]=sAh[(r+8)*16+ia];
                ah[mt][2]=sAh[r*16+(ia^4)]; ah[mt][3]=sAh[(r+8)*16+(ia^4)];
                al[mt][0]=sAl[r*16+ia]; al[mt][1]=sAl[(r+8)*16+ia];
                al[mt][2]=sAl[r*16+(ia^4)]; al[mt][3]=sAl[(r+8)*16+(ia^4)];
            }
#pragma unroll
            for(int nt=0;nt<4;nt++){
                int cb=wn*32+nt*8+g;
                int ib=(8*s+cq)^(((cb>>1)&3)<<2);
                unsigned bh0=sBh[cb*16+ib],bh1=sBh[cb*16+(ib^4)];
                unsigned bl0=sBl[cb*16+ib],bl1=sBl[cb*16+(ib^4)];
#pragma unroll
                for(int mt=0;mt<4;mt++){
                    mmab(C[mt][nt],ah[mt],bh0,bh1);
                    mmab(C[mt][nt],al[mt],bh0,bh1);
                    mmab(C[mt][nt],ah[mt],bl0,bl1);
                }
            }
        }
        __syncthreads();
    }
}

__global__ void __launch_bounds__(256,2) k_input(const float* __restrict__ bin_){
    __shared__ unsigned sm[8192];
    float C[4][4][4]={};
    gemmP(g_xh+(size_t)blockIdx.x*128*INP, g_xl+(size_t)blockIdx.x*128*INP, INP,
          g_winh+(size_t)blockIdx.y*128*INP, g_winl+(size_t)blockIdx.y*128*INP, INP, INP, sm, C);
    const int lane=threadIdx.x&31,w=threadIdx.x>>5,wm=w>>2,wn=w&3,g=lane>>2,cq=lane&3;
#pragma unroll
    for(int mt=0;mt<4;mt++)
#pragma unroll
    for(int nt=0;nt<4;nt++){
        int col=blockIdx.y*128+wn*32+nt*8+cq*2;
        float b0=bin_[col],b1=bin_[col+1];
#pragma unroll
        for(int hh=0;hh<2;hh++){
            int row=blockIdx.x*128+wm*64+mt*16+g+hh*8;
            float vx=C[mt][nt][hh*2]+b0, vy=C[mt][nt][hh*2+1]+b1;
            vx=(vx>0.f?vx:0.2f*vx)*10.f; vy=(vy>0.f?vy:0.2f*vy)*10.f;
            unsigned hi,lo; split2(vx,vy,hi,lo);
            *(unsigned*)&g_zh[(size_t)row*HH+col]=hi;
            *(unsigned*)&g_zl[(size_t)row*HH+col]=lo;
        }
    }
}

__global__ void __launch_bounds__(256,2) k_xg0(const float* __restrict__ b_ih0,
        const float* __restrict__ b_hh0){
    __shared__ unsigned sm[8192];
    int n=blockIdx.z;
    float C[4][4][4]={};
    size_t bo=((size_t)n*GG+(size_t)blockIdx.y*128)*HH;
    gemmP(g_zh+(size_t)blockIdx.x*128*HH, g_zl+(size_t)blockIdx.x*128*HH, HH,
          g_wih0h+bo, g_wih0l+bo, HH, HH, sm, C);
    const int lane=threadIdx.x&31,w=threadIdx.x>>5,wm=w>>2,wn=w&3,g=lane>>2,cq=lane&3;
#pragma unroll
    for(int mt=0;mt<4;mt++)
#pragma unroll
    for(int nt=0;nt<4;nt++){
        int gc=blockIdx.y*128+wn*32+nt*8+cq*2;
        float b0=b_ih0[(size_t)n*GG+gc]+b_hh0[(size_t)n*GG+gc];
        float b1=b_ih0[(size_t)n*GG+gc+1]+b_hh0[(size_t)n*GG+gc+1];
#pragma unroll
        for(int hh=0;hh<2;hh++){
            int grow=blockIdx.x*128+wm*64+mt*16+g+hh*8;
            int b=grow>>8, t=grow&255;
            float2 o; o.x=C[mt][nt][hh*2]+b0; o.y=C[mt][nt][hh*2+1]+b1;
            *(float2*)&g_xg0[(((size_t)t*NN+n)*BB+b)*GG+gc]=o;
        }
    }
}

__global__ void __launch_bounds__(256,2) k_heads1(const float* __restrict__ bh1){
    __shared__ unsigned sm[8192];
    int n=blockIdx.z;
    float C[4][4][4]={};
    size_t ao=(size_t)n*BB*TT*HH+(size_t)blockIdx.x*128*HH;
    size_t bo=((size_t)n*MM+(size_t)blockIdx.y*128)*HH;
    gemmP(g_yh+ao, g_yl+ao, HH, g_wh1h+bo, g_wh1l+bo, HH, HH, sm, C);
    const int lane=threadIdx.x&31,w=threadIdx.x>>5,wm=w>>2,wn=w&3,g=lane>>2,cq=lane&3;
#pragma unroll
    for(int mt=0;mt<4;mt++)
#pragma unroll
    for(int nt=0;nt<4;nt++){
        int m=blockIdx.y*128+wn*32+nt*8+cq*2;
        float b0=bh1[(size_t)n*MM+m],b1=bh1[(size_t)n*MM+m+1];
#pragma unroll
        for(int hh=0;hh<2;hh++){
            int row=blockIdx.x*128+wm*64+mt*16+g+hh*8;
            float vx=C[mt][nt][hh*2]+b0, vy=C[mt][nt][hh*2+1]+b1;
            float2 o; o.x=(vx>0.f?vx:0.2f*vx); o.y=(vy>0.f?vy:0.2f*vy);
            *(float2*)&g_hid[((size_t)n*BB*TT+row)*MM+m]=o;
        }
    }
}

// ============ recurrent GEMM: 64x128 tile, fp16, A single + B hi/lo, 2-mma ============
__device__ __forceinline__ void gemmR(const hf* __restrict__ Af,
        const hf* __restrict__ Bh,const hf* __restrict__ Bl,
        unsigned* sm,float(&C)[2][4][4]){
    unsigned* sA=sm; unsigned* sBh=sm+1024; unsigned* sBl=sm+3072;
    const int tid=threadIdx.x,lane=tid&31,w=tid>>5,wm=w>>2,wn=w&3,g=lane>>2,cq=lane&3;
    const int ar=tid>>2, a8=(tid&3)*8, akw=(tid&3)*4;
    uint4 pa,pbh[2],pbl[2];
    pa=*(const uint4*)(Af+(size_t)ar*HH+a8);
#pragma unroll
    for(int j=0;j<2;j++){int v=tid+j*256,row=v>>2,e8=(v&3)*8;
        pbh[j]=*(const uint4*)(Bh+(size_t)row*HH+e8);
        pbl[j]=*(const uint4*)(Bl+(size_t)row*HH+e8);}
    for(int c=0;c<16;c++){
        *(uint4*)&sA[SWZ(ar,akw)]=pa;
#pragma unroll
        for(int j=0;j<2;j++){int v=tid+j*256,row=v>>2,kw=(v&3)*4;
            *(uint4*)&sBh[SWZ(row,kw)]=pbh[j];
            *(uint4*)&sBl[SWZ(row,kw)]=pbl[j];}
        __syncthreads();
        if(c<15){int k0=(c+1)*32;
            pa=*(const uint4*)(Af+(size_t)ar*HH+k0+a8);
#pragma unroll
            for(int j=0;j<2;j++){int v=tid+j*256,row=v>>2,e8=(v&3)*8;
                pbh[j]=*(const uint4*)(Bh+(size_t)row*HH+k0+e8);
                pbl[j]=*(const uint4*)(Bl+(size_t)row*HH+k0+e8);}
        }
#pragma unroll
        for(int s=0;s<2;s++){
            unsigned a[2][4];
#pragma unroll
            for(int mt=0;mt<2;mt++){
                int r=wm*32+mt*16+g;
                int ia=(8*s+cq)^(((r>>1)&3)<<2);
                a[mt][0]=sA[r*16+ia]; a[mt][1]=sA[(r+8)*16+ia];
                a[mt][2]=sA[r*16+(ia^4)]; a[mt][3]=sA[(r+8)*16+(ia^4)];
            }
#pragma unroll
            for(int nt=0;nt<4;nt++){
                int cb=wn*32+nt*8+g;
                int ib=(8*s+cq)^(((cb>>1)&3)<<2);
                unsigned bh0=sBh[cb*16+ib],bh1=sBh[cb*16+(ib^4)];
                unsigned bl0=sBl[cb*16+ib],bl1=sBl[cb*16+(ib^4)];
#pragma unroll
                for(int mt=0;mt<2;mt++){
                    mmah(C[mt][nt],a[mt],bh0,bh1);
                    mmah(C[mt][nt],a[mt],bl0,bl1);
                }
            }
        }
        __syncthreads();
    }
}

__device__ __forceinline__ void stage_rec(float(&C)[2][4][4],float* sC){
    const int lane=threadIdx.x&31,w=threadIdx.x>>5,wm=w>>2,wn=w&3,g=lane>>2,cq=lane&3;
#pragma unroll
    for(int mt=0;mt<2;mt++){
        int r=wm*32+mt*16+g;
#pragma unroll
        for(int nt=0;nt<4;nt++){
            int col=wn*32+nt*8+cq*2;
            *(float2*)&sC[r*132+col]=make_float2(C[mt][nt][0],C[mt][nt][1]);
            *(float2*)&sC[(r+8)*132+col]=make_float2(C[mt][nt][2],C[mt][nt][3]);
        }
    }
}

__device__ __forceinline__ void grid_bar(unsigned nb){
    __syncthreads();
    if(threadIdx.x==0){
        __threadfence();
        unsigned gen=atomicAdd(&g_barg,0u);
        unsigned t=atomicAdd(&g_barc,1u);
        if(t==nb-1u){atomicExch(&g_barc,0u);__threadfence();atomicAdd(&g_barg,1u);}
        else{while(atomicAdd(&g_barg,0u)==gen){__nanosleep(64);}}
        __threadfence();
    }
    __syncthreads();
}

// ---------- persistent recurrent kernel: 128 blocks = (n, ct of 32 hidden) ----------
__global__ void __launch_bounds__(256) k_rec(const float* __restrict__ b_ih1,
        const float* __restrict__ b_hh1){
    __shared__ unsigned sm[8448];
    float* sC=(float*)sm;
    const int tid=threadIdx.x;
    const int n=blockIdx.x>>4, ct=blockIdx.x&15, hh0=ct*32;
    const unsigned nb=gridDim.x;
    const size_t ws=(size_t)128*HH;
    const hf* w0h=g_rwh+((size_t)(0*NN+n)*16+ct)*ws; const hf* w0l=g_rwl+((size_t)(0*NN+n)*16+ct)*ws;
    const hf* w1h=g_rwh+((size_t)(1*NN+n)*16+ct)*ws; const hf* w1l=g_rwl+((size_t)(1*NN+n)*16+ct)*ws;
    const hf* w2h=g_rwh+((size_t)(2*NN+n)*16+ct)*ws; const hf* w2l=g_rwl+((size_t)(2*NN+n)*16+ct)*ws;
    const float* bi1=b_ih1+(size_t)n*GG;
    const float* bh1g=b_hh1+(size_t)n*GG;
    const size_t st=(size_t)n*BB*HH;
    const int b=tid>>2, q=tid&3;

    for(int t=0;t<=TT;t++){
        int p=t&1;
        if(t>0){  // layer 1 for step t-1
            float C[2][4][4]={};
            gemmR(g_h0f[p]+st, w1h, w1l, sm, C);
            gemmR(g_h1f[p^1]+st, w2h, w2l, sm, C);
            stage_rec(C,sC);
            __syncthreads();
            size_t hb=st+(size_t)b*HH+hh0;
#pragma unroll
            for(int k=0;k<8;k++){
                int hl=q*8+k, h=hh0+hl;
                float pi=sC[b*132+hl*4+0]+bi1[h]+bh1g[h];
                float pf=sC[b*132+hl*4+1]+bi1[HH+h]+bh1g[HH+h];
                float pg=sC[b*132+hl*4+2]+bi1[2*HH+h]+bh1g[2*HH+h];
                float po=sC[b*132+hl*4+3]+bi1[3*HH+h]+bh1g[3*HH+h];
                float cn=sigf(pf)*g_c1[hb+hl]+sigf(pi)*tanhf(pg);
                float hn=sigf(po)*tanhf(cn);
                g_c1[hb+hl]=cn;
                g_h1f[p][hb+hl]=__float2half_rn(hn);
                bf hi=__float2bfloat16(hn);
                size_t yi=(((size_t)n*BB+b)*TT+(t-1))*HH+h;
                g_yh[yi]=hi; g_yl[yi]=__float2bfloat16(hn-__bfloat162float(hi));
            }
            __syncthreads();
        }
        if(t<TT){  // layer 0 for step t
            float C[2][4][4]={};
            gemmR(g_h0f[p]+st, w0h, w0l, sm, C);
            stage_rec(C,sC);
            __syncthreads();
            const float* xgb=g_xg0+(((size_t)t*NN+n)*BB+b)*GG;
            size_t hb=st+(size_t)b*HH+hh0;
#pragma unroll
            for(int k=0;k<8;k++){
                int hl=q*8+k, h=hh0+hl;
                float pi=sC[b*132+hl*4+0]+xgb[h];
                float pf=sC[b*132+hl*4+1]+xgb[HH+h];
                float pg=sC[b*132+hl*4+2]+xgb[2*HH+h];
                float po=sC[b*132+hl*4+3]+xgb[3*HH+h];
                float cn=sigf(pf)*g_c0[hb+hl]+sigf(pi)*tanhf(pg);
                float hn=sigf(po)*tanhf(cn);
                g_c0[hb+hl]=cn;
                g_h0f[p^1][hb+hl]=__float2half_rn(hn);
            }
            __syncthreads();
        }
        grid_bar(nb);
    }
}

__global__ void __launch_bounds__(256) k_heads2(const float* __restrict__ Wh2,
        const float* __restrict__ bh2,float* __restrict__ out){
    int gw=(blockIdx.x*blockDim.x+threadIdx.x)>>5;
    int lane=threadIdx.x&31;
    if(gw>=NN*BB*TT) return;
    int n=gw>>14;
    const float* hrow=g_hid+(size_t)gw*MM;
    float hv[16];
#pragma unroll
    for(int qq=0;qq<4;qq++){
        float4 v=*(const float4*)(hrow+lane*16+qq*4);
        hv[qq*4]=v.x;hv[qq*4+1]=v.y;hv[qq*4+2]=v.z;hv[qq*4+3]=v.w;
    }
    const float* W=Wh2+(size_t)n*OO*MM;
#pragma unroll
    for(int o=0;o<OO;o++){
        const float4* w4=(const float4*)(W+(size_t)o*MM+lane*16);
        float s=0.f;
#pragma unroll
        for(int qq=0;qq<4;qq++){
            float4 wv=w4[qq];
            s+=hv[qq*4]*wv.x+hv[qq*4+1]*wv.y+hv[qq*4+2]*wv.z+hv[qq*4+3]*wv.w;
        }
#pragma unroll
        for(int off=16;off>0;off>>=1) s+=__shfl_xor_sync(0xFFFFFFFFu,s,off);
        if(lane==0) out[(size_t)gw*OO+o]=s+bh2[(size_t)n*OO+o];
    }
}

extern "C" void kernel_launch(void* const* d_in, const int* in_sizes, int n_in,
                              void* d_out, int out_size){
    const float* x=(const float*)d_in[0];
    const float* Win=(const float*)d_in[1];
    const float* bin_=(const float*)d_in[2];
    const float* W_ih0=(const float*)d_in[3];
    const float* W_hh0=(const float*)d_in[4];
    const float* b_ih0=(const float*)d_in[5];
    const float* b_hh0=(const float*)d_in[6];
    const float* W_ih1=(const float*)d_in[7];
    const float* W_hh1=(const float*)d_in[8];
    const float* b_ih1=(const float*)d_in[9];
    const float* b_hh1=(const float*)d_in[10];
    const float* Wh1=(const float*)d_in[11];
    const float* bh1=(const float*)d_in[12];
    const float* Wh2=(const float*)d_in[13];
    const float* bh2=(const float*)d_in[14];
    float* out=(float*)d_out;

    k_init<<<256,256>>>();
    bf *xh,*xl,*winh,*winl,*wih0h,*wih0l,*wh1h,*wh1l;
    cudaGetSymbolAddress((void**)&xh,g_xh);     cudaGetSymbolAddress((void**)&xl,g_xl);
    cudaGetSymbolAddress((void**)&winh,g_winh); cudaGetSymbolAddress((void**)&winl,g_winl);
    cudaGetSymbolAddress((void**)&wih0h,g_wih0h); cudaGetSymbolAddress((void**)&wih0l,g_wih0l);
    cudaGetSymbolAddress((void**)&wh1h,g_wh1h); cudaGetSymbolAddress((void**)&wh1l,g_wh1l);
    k_split2<<<(BB*TT*INP+255)/256,256>>>(x,xh,xl,BB*TT*INP);
    k_split2<<<(HH*INP+255)/256,256>>>(Win,winh,winl,HH*INP);
    k_split2<<<(NN*GG*HH+255)/256,256>>>(W_ih0,wih0h,wih0l,NN*GG*HH);
    k_split2<<<(NN*MM*HH+255)/256,256>>>(Wh1,wh1h,wh1l,NN*MM*HH);
    k_split_rec<<<(int)(((size_t)3*NN*GG*HH+255)/256),256>>>(W_hh0,W_ih1,W_hh1);

    k_input<<<dim3(128,4),256>>>(bin_);
    k_xg0<<<dim3(128,16,NN),256>>>(b_ih0,b_hh0);
    k_rec<<<128,256>>>(b_ih1,b_hh1);
    k_heads1<<<dim3(128,4,NN),256>>>(bh1);
    k_heads2<<<(NN*BB*TT)/8,256>>>(Wh2,bh2,out);
}

// round 12
// speedup vs baseline: 4.5820x; 1.4666x over previous
#include <cuda_runtime.h>
#include <cuda_bf16.h>
#include <cuda_fp16.h>
#include <cstdint>
#include <math.h>

#define NN 8
#define BB 64
#define TT 256
#define INP 64
#define HH 512
#define GG 2048
#define MM 512
#define OO 7
typedef __nv_bfloat16 bf;
typedef __half hf;

// ---------------- globals ----------------
__device__ __align__(16) bf g_xh[(size_t)BB*TT*INP], g_xl[(size_t)BB*TT*INP];
__device__ __align__(16) bf g_winh[HH*INP], g_winl[HH*INP];
__device__ __align__(16) bf g_zh[(size_t)BB*TT*HH], g_zl[(size_t)BB*TT*HH];
__device__ __align__(16) bf g_wih0h[(size_t)NN*GG*HH], g_wih0l[(size_t)NN*GG*HH];
__device__ __align__(16) bf g_wh1h[(size_t)NN*MM*HH], g_wh1l[(size_t)NN*MM*HH];
// recurrent weights: SINGLE fp16, remapped [w][n][ct(16)][c(128)][k], c = hidden_local*4+gate
__device__ __align__(16) hf g_rw[(size_t)3*NN*GG*HH];
// recurrent h states: single fp16
__device__ __align__(16) hf g_h0f[2][NN*BB*HH], g_h1f[2][NN*BB*HH];
__device__ float g_c0[NN*BB*HH], g_c1[NN*BB*HH];
__device__ __align__(16) bf g_yh[(size_t)NN*BB*TT*HH], g_yl[(size_t)NN*BB*TT*HH];
__device__ float g_xg0[(size_t)TT*NN*BB*GG];
__device__ float g_hid[(size_t)NN*BB*TT*MM];
__device__ unsigned g_barc, g_barg;

__device__ __forceinline__ float sigf(float x){return 1.0f/(1.0f+expf(-x));}
#define SWZ(row,kw) (((row)<<4)+((kw)^((((row)>>1)&3)<<2)))

__device__ __forceinline__ void split2(float x,float y,unsigned&hi,unsigned&lo){
    __nv_bfloat162 h=__floats2bfloat162_rn(x,y);
    float hx=__low2float(h), hy=__high2float(h);
    __nv_bfloat162 l=__floats2bfloat162_rn(x-hx,y-hy);
    hi=*(unsigned*)&h; lo=*(unsigned*)&l;
}
__device__ __forceinline__ void mmab(float(&d)[4],const unsigned(&a)[4],unsigned b0,unsigned b1){
    asm volatile("mma.sync.aligned.m16n8k16.row.col.f32.bf16.bf16.f32 "
        "{%0,%1,%2,%3},{%4,%5,%6,%7},{%8,%9},{%0,%1,%2,%3};"
        :"+f"(d[0]),"+f"(d[1]),"+f"(d[2]),"+f"(d[3])
        :"r"(a[0]),"r"(a[1]),"r"(a[2]),"r"(a[3]),"r"(b0),"r"(b1));
}
__device__ __forceinline__ void mmah(float(&d)[4],const unsigned(&a)[4],unsigned b0,unsigned b1){
    asm volatile("mma.sync.aligned.m16n8k16.row.col.f32.f16.f16.f32 "
        "{%0,%1,%2,%3},{%4,%5,%6,%7},{%8,%9},{%0,%1,%2,%3};"
        :"+f"(d[0]),"+f"(d[1]),"+f"(d[2]),"+f"(d[3])
        :"r"(a[0]),"r"(a[1]),"r"(a[2]),"r"(a[3]),"r"(b0),"r"(b1));
}

__global__ void k_init(){
    int i=blockIdx.x*blockDim.x+threadIdx.x, st=gridDim.x*blockDim.x;
    for(int j=i;j<NN*BB*HH;j+=st){
        ((unsigned short*)g_h0f[0])[j]=0;((unsigned short*)g_h1f[0])[j]=0;
        g_c0[j]=0.f;g_c1[j]=0.f;
    }
    if(i==0){g_barc=0u;g_barg=0u;}
}

__global__ void k_split2(const float* __restrict__ s, bf* dh, bf* dl, int cnt){
    int i=blockIdx.x*blockDim.x+threadIdx.x;
    if(i<cnt){float v=s[i]; bf h=__float2bfloat16(v);
        dh[i]=h; dl[i]=__float2bfloat16(v-__bfloat162float(h));}
}

__global__ void k_split_rec(const float* __restrict__ W0,const float* __restrict__ W1,
                            const float* __restrict__ W2){
    size_t idx=(size_t)blockIdx.x*blockDim.x+threadIdx.x;
    if(idx>=(size_t)3*NN*GG*HH) return;
    int k=idx&511; int c=(int)((idx>>9)&127); int ct=(int)((idx>>16)&15);
    int n=(int)((idx>>20)&7); int w=(int)(idx>>23);
    int hidden=ct*32+(c>>2), gate=c&3;
    const float* W=(w==0)?W0:((w==1)?W1:W2);
    g_rw[idx]=__float2half_rn(W[((size_t)n*GG+gate*HH+hidden)*HH+k]);
}

// ============ parallel mma.sync GEMM: 128x128 tile, bf16 3-term ============
__device__ __forceinline__ void gemmP(const bf* __restrict__ Ah,const bf* __restrict__ Al,int lda,
        const bf* __restrict__ Bh,const bf* __restrict__ Bl,int ldb,int K,
        unsigned* sm,float(&C)[4][4][4]){
    unsigned* sAh=sm; unsigned* sAl=sm+2048; unsigned* sBh=sm+4096; unsigned* sBl=sm+6144;
    const int tid=threadIdx.x,lane=tid&31,w=tid>>5,wm=w>>2,wn=w&3,g=lane>>2,cq=lane&3;
    for(int k0=0;k0<K;k0+=32){
#pragma unroll
        for(int j=0;j<2;j++){
            int v=tid+j*256,row=v>>2,e8=(v&3)*8,kw=(v&3)*4;
            *(uint4*)&sAh[SWZ(row,kw)]=*(const uint4*)(Ah+(size_t)row*lda+k0+e8);
            *(uint4*)&sAl[SWZ(row,kw)]=*(const uint4*)(Al+(size_t)row*lda+k0+e8);
            *(uint4*)&sBh[SWZ(row,kw)]=*(const uint4*)(Bh+(size_t)row*ldb+k0+e8);
            *(uint4*)&sBl[SWZ(row,kw)]=*(const uint4*)(Bl+(size_t)row*ldb+k0+e8);
        }
        __syncthreads();
#pragma unroll
        for(int s=0;s<2;s++){
            unsigned ah[4][4],al[4][4];
#pragma unroll
            for(int mt=0;mt<4;mt++){
                int r=wm*64+mt*16+g;
                int ia=(8*s+cq)^(((r>>1)&3)<<2);
                ah[mt][0]=sAh[r*16+ia]; ah[mt][1]=sAh[(r+8)*16+ia];
                ah[mt][2]=sAh[r*16+(ia^4)]; ah[mt][3]=sAh[(r+8)*16+(ia^4)];
                al[mt][0]=sAl[r*16+ia]; al[mt][1]=sAl[(r+8)*16+ia];
                al[mt][2]=sAl[r*16+(ia^4)]; al[mt][3]=sAl[(r+8)*16+(ia^4)];
            }
#pragma unroll
            for(int nt=0;nt<4;nt++){
                int cb=wn*32+nt*8+g;
                int ib=(8*s+cq)^(((cb>>1)&3)<<2);
                unsigned bh0=sBh[cb*16+ib],bh1=sBh[cb*16+(ib^4)];
                unsigned bl0=sBl[cb*16+ib],bl1=sBl[cb*16+(ib^4)];
#pragma unroll
                for(int mt=0;mt<4;mt++){
                    mmab(C[mt][nt],ah[mt],bh0,bh1);
                    mmab(C[mt][nt],al[mt],bh0,bh1);
                    mmab(C[mt][nt],ah[mt],bl0,bl1);
                }
            }
        }
        __syncthreads();
    }
}

__global__ void __launch_bounds__(256,2) k_input(const float* __restrict__ bin_){
    __shared__ unsigned sm[8192];
    float C[4][4][4]={};
    gemmP(g_xh+(size_t)blockIdx.x*128*INP, g_xl+(size_t)blockIdx.x*128*INP, INP,
          g_winh+(size_t)blockIdx.y*128*INP, g_winl+(size_t)blockIdx.y*128*INP, INP, INP, sm, C);
    const int lane=threadIdx.x&31,w=threadIdx.x>>5,wm=w>>2,wn=w&3,g=lane>>2,cq=lane&3;
#pragma unroll
    for(int mt=0;mt<4;mt++)
#pragma unroll
    for(int nt=0;nt<4;nt++){
        int col=blockIdx.y*128+wn*32+nt*8+cq*2;
        float b0=bin_[col],b1=bin_[col+1];
#pragma unroll
        for(int hh=0;hh<2;hh++){
            int row=blockIdx.x*128+wm*64+mt*16+g+hh*8;
            float vx=C[mt][nt][hh*2]+b0, vy=C[mt][nt][hh*2+1]+b1;
            vx=(vx>0.f?vx:0.2f*vx)*10.f; vy=(vy>0.f?vy:0.2f*vy)*10.f;
            unsigned hi,lo; split2(vx,vy,hi,lo);
            *(unsigned*)&g_zh[(size_t)row*HH+col]=hi;
            *(unsigned*)&g_zl[(size_t)row*HH+col]=lo;
        }
    }
}

__global__ void __launch_bounds__(256,2) k_xg0(const float* __restrict__ b_ih0,
        const float* __restrict__ b_hh0){
    __shared__ unsigned sm[8192];
    int n=blockIdx.z;
    float C[4][4][4]={};
    size_t bo=((size_t)n*GG+(size_t)blockIdx.y*128)*HH;
    gemmP(g_zh+(size_t)blockIdx.x*128*HH, g_zl+(size_t)blockIdx.x*128*HH, HH,
          g_wih0h+bo, g_wih0l+bo, HH, HH, sm, C);
    const int lane=threadIdx.x&31,w=threadIdx.x>>5,wm=w>>2,wn=w&3,g=lane>>2,cq=lane&3;
#pragma unroll
    for(int mt=0;mt<4;mt++)
#pragma unroll
    for(int nt=0;nt<4;nt++){
        int gc=blockIdx.y*128+wn*32+nt*8+cq*2;
        float b0=b_ih0[(size_t)n*GG+gc]+b_hh0[(size_t)n*GG+gc];
        float b1=b_ih0[(size_t)n*GG+gc+1]+b_hh0[(size_t)n*GG+gc+1];
#pragma unroll
        for(int hh=0;hh<2;hh++){
            int grow=blockIdx.x*128+wm*64+mt*16+g+hh*8;
            int b=grow>>8, t=grow&255;
            float2 o; o.x=C[mt][nt][hh*2]+b0; o.y=C[mt][nt][hh*2+1]+b1;
            *(float2*)&g_xg0[(((size_t)t*NN+n)*BB+b)*GG+gc]=o;
        }
    }
}

__global__ void __launch_bounds__(256,2) k_heads1(const float* __restrict__ bh1){
    __shared__ unsigned sm[8192];
    int n=blockIdx.z;
    float C[4][4][4]={};
    size_t ao=(size_t)n*BB*TT*HH+(size_t)blockIdx.x*128*HH;
    size_t bo=((size_t)n*MM+(size_t)blockIdx.y*128)*HH;
    gemmP(g_yh+ao, g_yl+ao, HH, g_wh1h+bo, g_wh1l+bo, HH, HH, sm, C);
    const int lane=threadIdx.x&31,w=threadIdx.x>>5,wm=w>>2,wn=w&3,g=lane>>2,cq=lane&3;
#pragma unroll
    for(int mt=0;mt<4;mt++)
#pragma unroll
    for(int nt=0;nt<4;nt++){
        int m=blockIdx.y*128+wn*32+nt*8+cq*2;
        float b0=bh1[(size_t)n*MM+m],b1=bh1[(size_t)n*MM+m+1];
#pragma unroll
        for(int hh=0;hh<2;hh++){
            int row=blockIdx.x*128+wm*64+mt*16+g+hh*8;
            float vx=C[mt][nt][hh*2]+b0, vy=C[mt][nt][hh*2+1]+b1;
            float2 o; o.x=(vx>0.f?vx:0.2f*vx); o.y=(vy>0.f?vy:0.2f*vy);
            *(float2*)&g_hid[((size_t)n*BB*TT+row)*MM+m]=o;
        }
    }
}

// ============ recurrent GEMM: 64x128 tile, single fp16, K=128 groups ============
// buffer: A 4x4KB @ +0, B 4x8KB @ +16384; stride 49152; 1 sync/group.
__device__ __forceinline__ void gemmR(int nseg,
        const hf* __restrict__ A0,const hf* __restrict__ B0,
        const hf* __restrict__ A1,const hf* __restrict__ B1,
        char* S,float(&C)[2][4][4]){
    const int tid=threadIdx.x,lane=tid&31,w=tid>>5,wm=w>>2,wn=w&3,g=lane>>2,cq=lane&3;
    const int ar=tid>>2, ae=(tid&3)*8, akw=(tid&3)*4;
    uint4 ra[4], rb[4][2];
    auto pre=[&](int grp){
        int s=grp>>2, k0=(grp&3)*128;
        const hf* A=s?A1:A0; const hf* B=s?B1:B0;
#pragma unroll
        for(int i=0;i<4;i++){
            ra[i]=*(const uint4*)(A+(size_t)ar*HH+k0+i*32+ae);
#pragma unroll
            for(int j=0;j<2;j++){int v=tid+j*256;
                rb[i][j]=*(const uint4*)(B+(size_t)(v>>2)*HH+k0+i*32+(v&3)*8);}
        }
    };
    pre(0);
    int ng=nseg*4;
    for(int q=0;q<ng;q++){
        char* P=S+(q&1)*49152;
#pragma unroll
        for(int i=0;i<4;i++){
            *(uint4*)((unsigned*)(P+i*4096)+SWZ(ar,akw))=ra[i];
#pragma unroll
            for(int j=0;j<2;j++){int v=tid+j*256;
                *(uint4*)((unsigned*)(P+16384+i*8192)+SWZ(v>>2,(v&3)*4))=rb[i][j];}
        }
        __syncthreads();
        if(q+1<ng) pre(q+1);
#pragma unroll
        for(int i=0;i<4;i++){
            const unsigned* sA=(const unsigned*)(P+i*4096);
            const unsigned* sB=(const unsigned*)(P+16384+i*8192);
#pragma unroll
            for(int s=0;s<2;s++){
                unsigned a[2][4];
#pragma unroll
                for(int mt=0;mt<2;mt++){
                    int r=wm*32+mt*16+g;
                    int ia=(8*s+cq)^(((r>>1)&3)<<2);
                    a[mt][0]=sA[r*16+ia]; a[mt][1]=sA[(r+8)*16+ia];
                    a[mt][2]=sA[r*16+(ia^4)]; a[mt][3]=sA[(r+8)*16+(ia^4)];
                }
#pragma unroll
                for(int nt=0;nt<4;nt++){
                    int cb=wn*32+nt*8+g;
                    int ib=(8*s+cq)^(((cb>>1)&3)<<2);
                    unsigned b0=sB[cb*16+ib],b1=sB[cb*16+(ib^4)];
#pragma unroll
                    for(int mt=0;mt<2;mt++) mmah(C[mt][nt],a[mt],b0,b1);
                }
            }
        }
    }
    __syncthreads();
}

__device__ __forceinline__ void stage_rec(float(&C)[2][4][4],float* sC){
    const int lane=threadIdx.x&31,w=threadIdx.x>>5,wm=w>>2,wn=w&3,g=lane>>2,cq=lane&3;
#pragma unroll
    for(int mt=0;mt<2;mt++){
        int r=wm*32+mt*16+g;
#pragma unroll
        for(int nt=0;nt<4;nt++){
            int col=wn*32+nt*8+cq*2;
            *(float2*)&sC[r*132+col]=make_float2(C[mt][nt][0],C[mt][nt][1]);
            *(float2*)&sC[(r+8)*132+col]=make_float2(C[mt][nt][2],C[mt][nt][3]);
        }
    }
}

__device__ __forceinline__ void grid_bar(unsigned nb){
    __syncthreads();
    if(threadIdx.x==0){
        __threadfence();
        unsigned gen=atomicAdd(&g_barg,0u);
        unsigned t=atomicAdd(&g_barc,1u);
        if(t==nb-1u){atomicExch(&g_barc,0u);__threadfence();atomicAdd(&g_barg,1u);}
        else{while(atomicAdd(&g_barg,0u)==gen){__nanosleep(64);}}
        __threadfence();
    }
    __syncthreads();
}

// ---------- persistent recurrent kernel: 128 blocks = (n, ct of 32 hidden) ----------
__global__ void __launch_bounds__(256) k_rec(const float* __restrict__ b_ih1,
        const float* __restrict__ b_hh1){
    extern __shared__ __align__(16) char S[];
    float* sC=(float*)S;   // aliases buffer 0 (used only after gemmR's trailing sync)
    const int tid=threadIdx.x;
    const int n=blockIdx.x>>4, ct=blockIdx.x&15, hh0=ct*32;
    const unsigned nb=gridDim.x;
    const size_t ws=(size_t)128*HH;
    const hf* w0=g_rw+((size_t)(0*NN+n)*16+ct)*ws;
    const hf* w1=g_rw+((size_t)(1*NN+n)*16+ct)*ws;
    const hf* w2=g_rw+((size_t)(2*NN+n)*16+ct)*ws;
    const float* bi1=b_ih1+(size_t)n*GG;
    const float* bh1g=b_hh1+(size_t)n*GG;
    const size_t st=(size_t)n*BB*HH;
    const int b=tid>>2, q=tid&3;

    for(int t=0;t<=TT;t++){
        int p=t&1;
        if(t>0){  // layer 1 for step t-1
            float C[2][4][4]={};
            gemmR(2, g_h0f[p]+st, w1, g_h1f[p^1]+st, w2, S, C);
            stage_rec(C,sC);
            __syncthreads();
            size_t hb=st+(size_t)b*HH+hh0;
#pragma unroll
            for(int k=0;k<8;k++){
                int hl=q*8+k, h=hh0+hl;
                float pi=sC[b*132+hl*4+0]+bi1[h]+bh1g[h];
                float pf=sC[b*132+hl*4+1]+bi1[HH+h]+bh1g[HH+h];
                float pg=sC[b*132+hl*4+2]+bi1[2*HH+h]+bh1g[2*HH+h];
                float po=sC[b*132+hl*4+3]+bi1[3*HH+h]+bh1g[3*HH+h];
                float cn=sigf(pf)*g_c1[hb+hl]+sigf(pi)*tanhf(pg);
                float hn=sigf(po)*tanhf(cn);
                g_c1[hb+hl]=cn;
                g_h1f[p][hb+hl]=__float2half_rn(hn);
                bf hi=__float2bfloat16(hn);
                size_t yi=(((size_t)n*BB+b)*TT+(t-1))*HH+h;
                g_yh[yi]=hi; g_yl[yi]=__float2bfloat16(hn-__bfloat162float(hi));
            }
            __syncthreads();
        }
        if(t<TT){  // layer 0 for step t
            float C[2][4][4]={};
            gemmR(1, g_h0f[p]+st, w0, (const hf*)0, (const hf*)0, S, C);
            stage_rec(C,sC);
            __syncthreads();
            const float* xgb=g_xg0+(((size_t)t*NN+n)*BB+b)*GG;
            size_t hb=st+(size_t)b*HH+hh0;
#pragma unroll
            for(int k=0;k<8;k++){
                int hl=q*8+k, h=hh0+hl;
                float pi=sC[b*132+hl*4+0]+xgb[h];
                float pf=sC[b*132+hl*4+1]+xgb[HH+h];
                float pg=sC[b*132+hl*4+2]+xgb[2*HH+h];
                float po=sC[b*132+hl*4+3]+xgb[3*HH+h];
                float cn=sigf(pf)*g_c0[hb+hl]+sigf(pi)*tanhf(pg);
                float hn=sigf(po)*tanhf(cn);
                g_c0[hb+hl]=cn;
                g_h0f[p^1][hb+hl]=__float2half_rn(hn);
            }
            __syncthreads();
        }
        grid_bar(nb);
    }
}

__global__ void __launch_bounds__(256) k_heads2(const float* __restrict__ Wh2,
        const float* __restrict__ bh2,float* __restrict__ out){
    int gw=(blockIdx.x*blockDim.x+threadIdx.x)>>5;
    int lane=threadIdx.x&31;
    if(gw>=NN*BB*TT) return;
    int n=gw>>14;
    const float* hrow=g_hid+(size_t)gw*MM;
    float hv[16];
#pragma unroll
    for(int qq=0;qq<4;qq++){
        float4 v=*(const float4*)(hrow+lane*16+qq*4);
        hv[qq*4]=v.x;hv[qq*4+1]=v.y;hv[qq*4+2]=v.z;hv[qq*4+3]=v.w;
    }
    const float* W=Wh2+(size_t)n*OO*MM;
#pragma unroll
    for(int o=0;o<OO;o++){
        const float4* w4=(const float4*)(W+(size_t)o*MM+lane*16);
        float s=0.f;
#pragma unroll
        for(int qq=0;qq<4;qq++){
            float4 wv=w4[qq];
            s+=hv[qq*4]*wv.x+hv[qq*4+1]*wv.y+hv[qq*4+2]*wv.z+hv[qq*4+3]*wv.w;
        }
#pragma unroll
        for(int off=16;off>0;off>>=1) s+=__shfl_xor_sync(0xFFFFFFFFu,s,off);
        if(lane==0) out[(size_t)gw*OO+o]=s+bh2[(size_t)n*OO+o];
    }
}

extern "C" void kernel_launch(void* const* d_in, const int* in_sizes, int n_in,
                              void* d_out, int out_size){
    const float* x=(const float*)d_in[0];
    const float* Win=(const float*)d_in[1];
    const float* bin_=(const float*)d_in[2];
    const float* W_ih0=(const float*)d_in[3];
    const float* W_hh0=(const float*)d_in[4];
    const float* b_ih0=(const float*)d_in[5];
    const float* b_hh0=(const float*)d_in[6];
    const float* W_ih1=(const float*)d_in[7];
    const float* W_hh1=(const float*)d_in[8];
    const float* b_ih1=(const float*)d_in[9];
    const float* b_hh1=(const float*)d_in[10];
    const float* Wh1=(const float*)d_in[11];
    const float* bh1=(const float*)d_in[12];
    const float* Wh2=(const float*)d_in[13];
    const float* bh2=(const float*)d_in[14];
    float* out=(float*)d_out;

    static int smset=0;
    if(!smset){ cudaFuncSetAttribute(k_rec, cudaFuncAttributeMaxDynamicSharedMemorySize, 98304); smset=1; }

    k_init<<<256,256>>>();
    bf *xh,*xl,*winh,*winl,*wih0h,*wih0l,*wh1h,*wh1l;
    cudaGetSymbolAddress((void**)&xh,g_xh);     cudaGetSymbolAddress((void**)&xl,g_xl);
    cudaGetSymbolAddress((void**)&winh,g_winh); cudaGetSymbolAddress((void**)&winl,g_winl);
    cudaGetSymbolAddress((void**)&wih0h,g_wih0h); cudaGetSymbolAddress((void**)&wih0l,g_wih0l);
    cudaGetSymbolAddress((void**)&wh1h,g_wh1h); cudaGetSymbolAddress((void**)&wh1l,g_wh1l);
    k_split2<<<(BB*TT*INP+255)/256,256>>>(x,xh,xl,BB*TT*INP);
    k_split2<<<(HH*INP+255)/256,256>>>(Win,winh,winl,HH*INP);
    k_split2<<<(NN*GG*HH+255)/256,256>>>(W_ih0,wih0h,wih0l,NN*GG*HH);
    k_split2<<<(NN*MM*HH+255)/256,256>>>(Wh1,wh1h,wh1l,NN*MM*HH);
    k_split_rec<<<(int)(((size_t)3*NN*GG*HH+255)/256),256>>>(W_hh0,W_ih1,W_hh1);

    k_input<<<dim3(128,4),256>>>(bin_);
    k_xg0<<<dim3(128,16,NN),256>>>(b_ih0,b_hh0);
    k_rec<<<128,256,98304>>>(b_ih1,b_hh1);
    k_heads1<<<dim3(128,4,NN),256>>>(bh1);
    k_heads2<<<(NN*BB*TT)/8,256>>>(Wh2,bh2,out);
}

// round 13
// speedup vs baseline: 5.2765x; 1.1516x over previous
#include <cuda_runtime.h>
#include <cuda_bf16.h>
#include <cuda_fp16.h>
#include <cstdint>
#include <math.h>

#define NN 8
#define BB 64
#define TT 256
#define INP 64
#define HH 512
#define GG 2048
#define MM 512
#define OO 7
typedef __nv_bfloat16 bf;
typedef __half hf;

// ---------------- globals ----------------
__device__ __align__(16) bf g_xh[(size_t)BB*TT*INP], g_xl[(size_t)BB*TT*INP];
__device__ __align__(16) bf g_winh[HH*INP], g_winl[HH*INP];
__device__ __align__(16) hf g_zf[(size_t)BB*TT*HH];                  // z single fp16
__device__ __align__(16) hf g_wih0f[(size_t)NN*GG*HH];               // W_ih0 single fp16
__device__ __align__(16) bf g_wh1h[(size_t)NN*MM*HH], g_wh1l[(size_t)NN*MM*HH];
// recurrent weights: SINGLE fp16, remapped [w][n][ct(16)][c(128)][k], c = hidden_local*4+gate
__device__ __align__(16) hf g_rw[(size_t)3*NN*GG*HH];
__device__ __align__(16) hf g_h0f[2][NN*BB*HH], g_h1f[2][NN*BB*HH];
__device__ float g_c0[NN*BB*HH], g_c1[NN*BB*HH];
__device__ __align__(16) bf g_yh[(size_t)NN*BB*TT*HH], g_yl[(size_t)NN*BB*TT*HH];
__device__ float g_xg0[(size_t)TT*NN*BB*GG];
__device__ float g_hid[(size_t)NN*BB*TT*MM];
__device__ unsigned g_barc, g_barg;

__device__ __forceinline__ float sigf(float x){return 1.0f/(1.0f+expf(-x));}
#define SWZ(row,kw) (((row)<<4)+((kw)^((((row)>>1)&3)<<2)))

__device__ __forceinline__ void split2(float x,float y,unsigned&hi,unsigned&lo){
    __nv_bfloat162 h=__floats2bfloat162_rn(x,y);
    float hx=__low2float(h), hy=__high2float(h);
    __nv_bfloat162 l=__floats2bfloat162_rn(x-hx,y-hy);
    hi=*(unsigned*)&h; lo=*(unsigned*)&l;
}
__device__ __forceinline__ void mmab(float(&d)[4],const unsigned(&a)[4],unsigned b0,unsigned b1){
    asm volatile("mma.sync.aligned.m16n8k16.row.col.f32.bf16.bf16.f32 "
        "{%0,%1,%2,%3},{%4,%5,%6,%7},{%8,%9},{%0,%1,%2,%3};"
        :"+f"(d[0]),"+f"(d[1]),"+f"(d[2]),"+f"(d[3])
        :"r"(a[0]),"r"(a[1]),"r"(a[2]),"r"(a[3]),"r"(b0),"r"(b1));
}
__device__ __forceinline__ void mmah(float(&d)[4],const unsigned(&a)[4],unsigned b0,unsigned b1){
    asm volatile("mma.sync.aligned.m16n8k16.row.col.f32.f16.f16.f32 "
        "{%0,%1,%2,%3},{%4,%5,%6,%7},{%8,%9},{%0,%1,%2,%3};"
        :"+f"(d[0]),"+f"(d[1]),"+f"(d[2]),"+f"(d[3])
        :"r"(a[0]),"r"(a[1]),"r"(a[2]),"r"(a[3]),"r"(b0),"r"(b1));
}

__global__ void k_init(){
    int i=blockIdx.x*blockDim.x+threadIdx.x, st=gridDim.x*blockDim.x;
    for(int j=i;j<NN*BB*HH;j+=st){
        ((unsigned short*)g_h0f[0])[j]=0;((unsigned short*)g_h1f[0])[j]=0;
        g_c0[j]=0.f;g_c1[j]=0.f;
    }
    if(i==0){g_barc=0u;g_barg=0u;}
}

__global__ void k_split2(const float* __restrict__ s, bf* dh, bf* dl, int cnt){
    int i=blockIdx.x*blockDim.x+threadIdx.x;
    if(i<cnt){float v=s[i]; bf h=__float2bfloat16(v);
        dh[i]=h; dl[i]=__float2bfloat16(v-__bfloat162float(h));}
}
__global__ void k_split1(const float* __restrict__ s, hf* d, int cnt){
    int i=blockIdx.x*blockDim.x+threadIdx.x;
    if(i<cnt) d[i]=__float2half_rn(s[i]);
}

__global__ void k_split_rec(const float* __restrict__ W0,const float* __restrict__ W1,
                            const float* __restrict__ W2){
    size_t idx=(size_t)blockIdx.x*blockDim.x+threadIdx.x;
    if(idx>=(size_t)3*NN*GG*HH) return;
    int k=idx&511; int c=(int)((idx>>9)&127); int ct=(int)((idx>>16)&15);
    int n=(int)((idx>>20)&7); int w=(int)(idx>>23);
    int hidden=ct*32+(c>>2), gate=c&3;
    const float* W=(w==0)?W0:((w==1)?W1:W2);
    g_rw[idx]=__float2half_rn(W[((size_t)n*GG+gate*HH+hidden)*HH+k]);
}

// ============ parallel bf16 3-term GEMM: 128x128 tile ============
__device__ __forceinline__ void gemmP(const bf* __restrict__ Ah,const bf* __restrict__ Al,int lda,
        const bf* __restrict__ Bh,const bf* __restrict__ Bl,int ldb,int K,
        unsigned* sm,float(&C)[4][4][4]){
    unsigned* sAh=sm; unsigned* sAl=sm+2048; unsigned* sBh=sm+4096; unsigned* sBl=sm+6144;
    const int tid=threadIdx.x,lane=tid&31,w=tid>>5,wm=w>>2,wn=w&3,g=lane>>2,cq=lane&3;
    for(int k0=0;k0<K;k0+=32){
#pragma unroll
        for(int j=0;j<2;j++){
            int v=tid+j*256,row=v>>2,e8=(v&3)*8,kw=(v&3)*4;
            *(uint4*)&sAh[SWZ(row,kw)]=*(const uint4*)(Ah+(size_t)row*lda+k0+e8);
            *(uint4*)&sAl[SWZ(row,kw)]=*(const uint4*)(Al+(size_t)row*lda+k0+e8);
            *(uint4*)&sBh[SWZ(row,kw)]=*(const uint4*)(Bh+(size_t)row*ldb+k0+e8);
            *(uint4*)&sBl[SWZ(row,kw)]=*(const uint4*)(Bl+(size_t)row*ldb+k0+e8);
        }
        __syncthreads();
#pragma unroll
        for(int s=0;s<2;s++){
            unsigned ah[4][4],al[4][4];
#pragma unroll
            for(int mt=0;mt<4;mt++){
                int r=wm*64+mt*16+g;
                int ia=(8*s+cq)^(((r>>1)&3)<<2);
                ah[mt][0]=sAh[r*16+ia]; ah[mt][1]=sAh[(r+8)*16+ia];
                ah[mt][2]=sAh[r*16+(ia^4)]; ah[mt][3]=sAh[(r+8)*16+(ia^4)];
                al[mt][0]=sAl[r*16+ia]; al[mt][1]=sAl[(r+8)*16+ia];
                al[mt][2]=sAl[r*16+(ia^4)]; al[mt][3]=sAl[(r+8)*16+(ia^4)];
            }
#pragma unroll
            for(int nt=0;nt<4;nt++){
                int cb=wn*32+nt*8+g;
                int ib=(8*s+cq)^(((cb>>1)&3)<<2);
                unsigned bh0=sBh[cb*16+ib],bh1=sBh[cb*16+(ib^4)];
                unsigned bl0=sBl[cb*16+ib],bl1=sBl[cb*16+(ib^4)];
#pragma unroll
                for(int mt=0;mt<4;mt++){
                    mmab(C[mt][nt],ah[mt],bh0,bh1);
                    mmab(C[mt][nt],al[mt],bh0,bh1);
                    mmab(C[mt][nt],ah[mt],bl0,bl1);
                }
            }
        }
        __syncthreads();
    }
}

// ============ parallel single-fp16 GEMM: 128x128 tile, 1 mma ============
__device__ __forceinline__ void gemmPH(const hf* __restrict__ A,int lda,
        const hf* __restrict__ B,int ldb,int K,
        unsigned* sm,float(&C)[4][4][4]){
    unsigned* sA=sm; unsigned* sB=sm+2048;
    const int tid=threadIdx.x,lane=tid&31,w=tid>>5,wm=w>>2,wn=w&3,g=lane>>2,cq=lane&3;
    for(int k0=0;k0<K;k0+=32){
#pragma unroll
        for(int j=0;j<2;j++){
            int v=tid+j*256,row=v>>2,e8=(v&3)*8,kw=(v&3)*4;
            *(uint4*)&sA[SWZ(row,kw)]=*(const uint4*)(A+(size_t)row*lda+k0+e8);
            *(uint4*)&sB[SWZ(row,kw)]=*(const uint4*)(B+(size_t)row*ldb+k0+e8);
        }
        __syncthreads();
#pragma unroll
        for(int s=0;s<2;s++){
            unsigned a[4][4];
#pragma unroll
            for(int mt=0;mt<4;mt++){
                int r=wm*64+mt*16+g;
                int ia=(8*s+cq)^(((r>>1)&3)<<2);
                a[mt][0]=sA[r*16+ia]; a[mt][1]=sA[(r+8)*16+ia];
                a[mt][2]=sA[r*16+(ia^4)]; a[mt][3]=sA[(r+8)*16+(ia^4)];
            }
#pragma unroll
            for(int nt=0;nt<4;nt++){
                int cb=wn*32+nt*8+g;
                int ib=(8*s+cq)^(((cb>>1)&3)<<2);
                unsigned b0=sB[cb*16+ib],b1=sB[cb*16+(ib^4)];
#pragma unroll
                for(int mt=0;mt<4;mt++) mmah(C[mt][nt],a[mt],b0,b1);
            }
        }
        __syncthreads();
    }
}

// ---------- input: z = leaky(x @ Win^T + bin)*10, stored single fp16 ----------
__global__ void __launch_bounds__(256,2) k_input(const float* __restrict__ bin_){
    __shared__ unsigned sm[8192];
    float C[4][4][4]={};
    gemmP(g_xh+(size_t)blockIdx.x*128*INP, g_xl+(size_t)blockIdx.x*128*INP, INP,
          g_winh+(size_t)blockIdx.y*128*INP, g_winl+(size_t)blockIdx.y*128*INP, INP, INP, sm, C);
    const int lane=threadIdx.x&31,w=threadIdx.x>>5,wm=w>>2,wn=w&3,g=lane>>2,cq=lane&3;
#pragma unroll
    for(int mt=0;mt<4;mt++)
#pragma unroll
    for(int nt=0;nt<4;nt++){
        int col=blockIdx.y*128+wn*32+nt*8+cq*2;
        float b0=bin_[col],b1=bin_[col+1];
#pragma unroll
        for(int hh=0;hh<2;hh++){
            int row=blockIdx.x*128+wm*64+mt*16+g+hh*8;
            float vx=C[mt][nt][hh*2]+b0, vy=C[mt][nt][hh*2+1]+b1;
            vx=(vx>0.f?vx:0.2f*vx)*10.f; vy=(vy>0.f?vy:0.2f*vy)*10.f;
            __half2 o=__floats2half2_rn(vx,vy);
            *(__half2*)&g_zf[(size_t)row*HH+col]=o;
        }
    }
}

// ---------- xg0: single-fp16 1-mma ----------
__global__ void __launch_bounds__(256,2) k_xg0(const float* __restrict__ b_ih0,
        const float* __restrict__ b_hh0){
    __shared__ unsigned sm[4096];
    int n=blockIdx.z;
    float C[4][4][4]={};
    gemmPH(g_zf+(size_t)blockIdx.x*128*HH, HH,
           g_wih0f+((size_t)n*GG+(size_t)blockIdx.y*128)*HH, HH, HH, sm, C);
    const int lane=threadIdx.x&31,w=threadIdx.x>>5,wm=w>>2,wn=w&3,g=lane>>2,cq=lane&3;
#pragma unroll
    for(int mt=0;mt<4;mt++)
#pragma unroll
    for(int nt=0;nt<4;nt++){
        int gc=blockIdx.y*128+wn*32+nt*8+cq*2;
        float b0=b_ih0[(size_t)n*GG+gc]+b_hh0[(size_t)n*GG+gc];
        float b1=b_ih0[(size_t)n*GG+gc+1]+b_hh0[(size_t)n*GG+gc+1];
#pragma unroll
        for(int hh=0;hh<2;hh++){
            int grow=blockIdx.x*128+wm*64+mt*16+g+hh*8;
            int b=grow>>8, t=grow&255;
            float2 o; o.x=C[mt][nt][hh*2]+b0; o.y=C[mt][nt][hh*2+1]+b1;
            *(float2*)&g_xg0[(((size_t)t*NN+n)*BB+b)*GG+gc]=o;
        }
    }
}

// ---------- heads1: keep bf16 3-term (error goes straight to output) ----------
__global__ void __launch_bounds__(256,2) k_heads1(const float* __restrict__ bh1){
    __shared__ unsigned sm[8192];
    int n=blockIdx.z;
    float C[4][4][4]={};
    size_t ao=(size_t)n*BB*TT*HH+(size_t)blockIdx.x*128*HH;
    size_t bo=((size_t)n*MM+(size_t)blockIdx.y*128)*HH;
    gemmP(g_yh+ao, g_yl+ao, HH, g_wh1h+bo, g_wh1l+bo, HH, HH, sm, C);
    const int lane=threadIdx.x&31,w=threadIdx.x>>5,wm=w>>2,wn=w&3,g=lane>>2,cq=lane&3;
#pragma unroll
    for(int mt=0;mt<4;mt++)
#pragma unroll
    for(int nt=0;nt<4;nt++){
        int m=blockIdx.y*128+wn*32+nt*8+cq*2;
        float b0=bh1[(size_t)n*MM+m],b1=bh1[(size_t)n*MM+m+1];
#pragma unroll
        for(int hh=0;hh<2;hh++){
            int row=blockIdx.x*128+wm*64+mt*16+g+hh*8;
            float vx=C[mt][nt][hh*2]+b0, vy=C[mt][nt][hh*2+1]+b1;
            float2 o; o.x=(vx>0.f?vx:0.2f*vx); o.y=(vy>0.f?vy:0.2f*vy);
            *(float2*)&g_hid[((size_t)n*BB*TT+row)*MM+m]=o;
        }
    }
}

// ============ recurrent GEMM: 64x128 tile, single fp16, K=128 groups ============
__device__ __forceinline__ void gemmR(int nseg,
        const hf* __restrict__ A0,const hf* __restrict__ B0,
        const hf* __restrict__ A1,const hf* __restrict__ B1,
        char* S,float(&C)[2][4][4]){
    const int tid=threadIdx.x,lane=tid&31,w=tid>>5,wm=w>>2,wn=w&3,g=lane>>2,cq=lane&3;
    const int ar=tid>>2, ae=(tid&3)*8, akw=(tid&3)*4;
    uint4 ra[4], rb[4][2];
    auto pre=[&](int grp){
        int s=grp>>2, k0=(grp&3)*128;
        const hf* A=s?A1:A0; const hf* B=s?B1:B0;
#pragma unroll
        for(int i=0;i<4;i++){
            ra[i]=*(const uint4*)(A+(size_t)ar*HH+k0+i*32+ae);
#pragma unroll
            for(int j=0;j<2;j++){int v=tid+j*256;
                rb[i][j]=*(const uint4*)(B+(size_t)(v>>2)*HH+k0+i*32+(v&3)*8);}
        }
    };
    pre(0);
    int ng=nseg*4;
    for(int q=0;q<ng;q++){
        char* P=S+(q&1)*49152;
#pragma unroll
        for(int i=0;i<4;i++){
            *(uint4*)((unsigned*)(P+i*4096)+SWZ(ar,akw))=ra[i];
#pragma unroll
            for(int j=0;j<2;j++){int v=tid+j*256;
                *(uint4*)((unsigned*)(P+16384+i*8192)+SWZ(v>>2,(v&3)*4))=rb[i][j];}
        }
        __syncthreads();
        if(q+1<ng) pre(q+1);
#pragma unroll
        for(int i=0;i<4;i++){
            const unsigned* sA=(const unsigned*)(P+i*4096);
            const unsigned* sB=(const unsigned*)(P+16384+i*8192);
#pragma unroll
            for(int s=0;s<2;s++){
                unsigned a[2][4];
#pragma unroll
                for(int mt=0;mt<2;mt++){
                    int r=wm*32+mt*16+g;
                    int ia=(8*s+cq)^(((r>>1)&3)<<2);
                    a[mt][0]=sA[r*16+ia]; a[mt][1]=sA[(r+8)*16+ia];
                    a[mt][2]=sA[r*16+(ia^4)]; a[mt][3]=sA[(r+8)*16+(ia^4)];
                }
#pragma unroll
                for(int nt=0;nt<4;nt++){
                    int cb=wn*32+nt*8+g;
                    int ib=(8*s+cq)^(((cb>>1)&3)<<2);
                    unsigned b0=sB[cb*16+ib],b1=sB[cb*16+(ib^4)];
#pragma unroll
                    for(int mt=0;mt<2;mt++) mmah(C[mt][nt],a[mt],b0,b1);
                }
            }
        }
    }
    __syncthreads();
}

__device__ __forceinline__ void stage_rec(float(&C)[2][4][4],float* sC){
    const int lane=threadIdx.x&31,w=threadIdx.x>>5,wm=w>>2,wn=w&3,g=lane>>2,cq=lane&3;
#pragma unroll
    for(int mt=0;mt<2;mt++){
        int r=wm*32+mt*16+g;
#pragma unroll
        for(int nt=0;nt<4;nt++){
            int col=wn*32+nt*8+cq*2;
            *(float2*)&sC[r*132+col]=make_float2(C[mt][nt][0],C[mt][nt][1]);
            *(float2*)&sC[(r+8)*132+col]=make_float2(C[mt][nt][2],C[mt][nt][3]);
        }
    }
}

__device__ __forceinline__ void grid_bar(unsigned nb){
    __syncthreads();
    if(threadIdx.x==0){
        __threadfence();
        unsigned gen=atomicAdd(&g_barg,0u);
        unsigned t=atomicAdd(&g_barc,1u);
        if(t==nb-1u){atomicExch(&g_barc,0u);__threadfence();atomicAdd(&g_barg,1u);}
        else{while(atomicAdd(&g_barg,0u)==gen){__nanosleep(64);}}
        __threadfence();
    }
    __syncthreads();
}

// ---------- persistent recurrent kernel: 128 blocks = (n, ct of 32 hidden) ----------
__global__ void __launch_bounds__(256) k_rec(const float* __restrict__ b_ih1,
        const float* __restrict__ b_hh1){
    extern __shared__ __align__(16) char S[];
    float* sC=(float*)S;
    const int tid=threadIdx.x;
    const int n=blockIdx.x>>4, ct=blockIdx.x&15, hh0=ct*32;
    const unsigned nb=gridDim.x;
    const size_t ws=(size_t)128*HH;
    const hf* w0=g_rw+((size_t)(0*NN+n)*16+ct)*ws;
    const hf* w1=g_rw+((size_t)(1*NN+n)*16+ct)*ws;
    const hf* w2=g_rw+((size_t)(2*NN+n)*16+ct)*ws;
    const float* bi1=b_ih1+(size_t)n*GG;
    const float* bh1g=b_hh1+(size_t)n*GG;
    const size_t st=(size_t)n*BB*HH;
    const int b=tid>>2, q=tid&3;

    for(int t=0;t<=TT;t++){
        int p=t&1;
        if(t>0){  // layer 1 for step t-1
            float C[2][4][4]={};
            gemmR(2, g_h0f[p]+st, w1, g_h1f[p^1]+st, w2, S, C);
            stage_rec(C,sC);
            __syncthreads();
            size_t hb=st+(size_t)b*HH+hh0;
#pragma unroll
            for(int k=0;k<8;k++){
                int hl=q*8+k, h=hh0+hl;
                float pi=sC[b*132+hl*4+0]+bi1[h]+bh1g[h];
                float pf=sC[b*132+hl*4+1]+bi1[HH+h]+bh1g[HH+h];
                float pg=sC[b*132+hl*4+2]+bi1[2*HH+h]+bh1g[2*HH+h];
                float po=sC[b*132+hl*4+3]+bi1[3*HH+h]+bh1g[3*HH+h];
                float cn=sigf(pf)*g_c1[hb+hl]+sigf(pi)*tanhf(pg);
                float hn=sigf(po)*tanhf(cn);
                g_c1[hb+hl]=cn;
                g_h1f[p][hb+hl]=__float2half_rn(hn);
                bf hi=__float2bfloat16(hn);
                size_t yi=(((size_t)n*BB+b)*TT+(t-1))*HH+h;
                g_yh[yi]=hi; g_yl[yi]=__float2bfloat16(hn-__bfloat162float(hi));
            }
            __syncthreads();
        }
        if(t<TT){  // layer 0 for step t
            float C[2][4][4]={};
            gemmR(1, g_h0f[p]+st, w0, (const hf*)0, (const hf*)0, S, C);
            stage_rec(C,sC);
            __syncthreads();
            const float* xgb=g_xg0+(((size_t)t*NN+n)*BB+b)*GG;
            size_t hb=st+(size_t)b*HH+hh0;
#pragma unroll
            for(int k=0;k<8;k++){
                int hl=q*8+k, h=hh0+hl;
                float pi=sC[b*132+hl*4+0]+xgb[h];
                float pf=sC[b*132+hl*4+1]+xgb[HH+h];
                float pg=sC[b*132+hl*4+2]+xgb[2*HH+h];
                float po=sC[b*132+hl*4+3]+xgb[3*HH+h];
                float cn=sigf(pf)*g_c0[hb+hl]+sigf(pi)*tanhf(pg);
                float hn=sigf(po)*tanhf(cn);
                g_c0[hb+hl]=cn;
                g_h0f[p^1][hb+hl]=__float2half_rn(hn);
            }
            __syncthreads();
        }
        grid_bar(nb);
    }
}

__global__ void __launch_bounds__(256) k_heads2(const float* __restrict__ Wh2,
        const float* __restrict__ bh2,float* __restrict__ out){
    int gw=(blockIdx.x*blockDim.x+threadIdx.x)>>5;
    int lane=threadIdx.x&31;
    if(gw>=NN*BB*TT) return;
    int n=gw>>14;
    const float* hrow=g_hid+(size_t)gw*MM;
    float hv[16];
#pragma unroll
    for(int qq=0;qq<4;qq++){
        float4 v=*(const float4*)(hrow+lane*16+qq*4);
        hv[qq*4]=v.x;hv[qq*4+1]=v.y;hv[qq*4+2]=v.z;hv[qq*4+3]=v.w;
    }
    const float* W=Wh2+(size_t)n*OO*MM;
#pragma unroll
    for(int o=0;o<OO;o++){
        const float4* w4=(const float4*)(W+(size_t)o*MM+lane*16);
        float s=0.f;
#pragma unroll
        for(int qq=0;qq<4;qq++){
            float4 wv=w4[qq];
            s+=hv[qq*4]*wv.x+hv[qq*4+1]*wv.y+hv[qq*4+2]*wv.z+hv[qq*4+3]*wv.w;
        }
#pragma unroll
        for(int off=16;off>0;off>>=1) s+=__shfl_xor_sync(0xFFFFFFFFu,s,off);
        if(lane==0) out[(size_t)gw*OO+o]=s+bh2[(size_t)n*OO+o];
    }
}

extern "C" void kernel_launch(void* const* d_in, const int* in_sizes, int n_in,
                              void* d_out, int out_size){
    const float* x=(const float*)d_in[0];
    const float* Win=(const float*)d_in[1];
    const float* bin_=(const float*)d_in[2];
    const float* W_ih0=(const float*)d_in[3];
    const float* W_hh0=(const float*)d_in[4];
    const float* b_ih0=(const float*)d_in[5];
    const float* b_hh0=(const float*)d_in[6];
    const float* W_ih1=(const float*)d_in[7];
    const float* W_hh1=(const float*)d_in[8];
    const float* b_ih1=(const float*)d_in[9];
    const float* b_hh1=(const float*)d_in[10];
    const float* Wh1=(const float*)d_in[11];
    const float* bh1=(const float*)d_in[12];
    const float* Wh2=(const float*)d_in[13];
    const float* bh2=(const float*)d_in[14];
    float* out=(float*)d_out;

    static int smset=0;
    if(!smset){ cudaFuncSetAttribute(k_rec, cudaFuncAttributeMaxDynamicSharedMemorySize, 98304); smset=1; }

    k_init<<<256,256>>>();
    bf *xh,*xl,*winh,*winl,*wh1h,*wh1l; hf *wih0f;
    cudaGetSymbolAddress((void**)&xh,g_xh);     cudaGetSymbolAddress((void**)&xl,g_xl);
    cudaGetSymbolAddress((void**)&winh,g_winh); cudaGetSymbolAddress((void**)&winl,g_winl);
    cudaGetSymbolAddress((void**)&wih0f,g_wih0f);
    cudaGetSymbolAddress((void**)&wh1h,g_wh1h); cudaGetSymbolAddress((void**)&wh1l,g_wh1l);
    k_split2<<<(BB*TT*INP+255)/256,256>>>(x,xh,xl,BB*TT*INP);
    k_split2<<<(HH*INP+255)/256,256>>>(Win,winh,winl,HH*INP);
    k_split1<<<(NN*GG*HH+255)/256,256>>>(W_ih0,wih0f,NN*GG*HH);
    k_split2<<<(NN*MM*HH+255)/256,256>>>(Wh1,wh1h,wh1l,NN*MM*HH);
    k_split_rec<<<(int)(((size_t)3*NN*GG*HH+255)/256),256>>>(W_hh0,W_ih1,W_hh1);

    k_input<<<dim3(128,4),256>>>(bin_);
    k_xg0<<<dim3(128,16,NN),256>>>(b_ih0,b_hh0);
    k_rec<<<128,256,98304>>>(b_ih1,b_hh1);
    k_heads1<<<dim3(128,4,NN),256>>>(bh1);
    k_heads2<<<(NN*BB*TT)/8,256>>>(Wh2,bh2,out);
}